// round 1
// baseline (speedup 1.0000x reference)
#include <cuda_runtime.h>
#include <math.h>

#define N_POINTS 20000
#define NUM_CLASSES 20
#define KNN 16
#define ITERS 3
#define TILE 2048

// scratch (no allocation allowed)
__device__ int   g_knn[N_POINTS * KNN];
__device__ float g_q[2][N_POINTS * NUM_CLASSES];

// ---------------------------------------------------------------------------
// KNN: one thread per query point; top-16 kept sorted in registers.
// Candidates staged in smem as float4 (broadcast reads, conflict-free).
// ---------------------------------------------------------------------------
__global__ void __launch_bounds__(128) knn_kernel(const float* __restrict__ coords)
{
    __shared__ float4 s_c[TILE];

    const int qi = blockIdx.x * blockDim.x + threadIdx.x;
    float qx = 0.f, qy = 0.f, qz = 0.f;
    if (qi < N_POINTS) {
        qx = coords[3 * qi + 0];
        qy = coords[3 * qi + 1];
        qz = coords[3 * qi + 2];
    }

    float bd[KNN];
    int   bi[KNN];
#pragma unroll
    for (int j = 0; j < KNN; ++j) { bd[j] = 3.4e38f; bi[j] = -1; }

    for (int base = 0; base < N_POINTS; base += TILE) {
        const int cnt = min(TILE, N_POINTS - base);
        __syncthreads();
        for (int t = threadIdx.x; t < cnt; t += blockDim.x) {
            const int g = base + t;
            s_c[t] = make_float4(coords[3 * g + 0], coords[3 * g + 1], coords[3 * g + 2], 0.f);
        }
        __syncthreads();

        int t = 0;
        // 4-way unroll for ILP (cnt here is always a multiple of 4: 2048 / 1568)
        for (; t + 3 < cnt; t += 4) {
            float4 c0 = s_c[t + 0];
            float4 c1 = s_c[t + 1];
            float4 c2 = s_c[t + 2];
            float4 c3 = s_c[t + 3];
            float dx0 = qx - c0.x, dy0 = qy - c0.y, dz0 = qz - c0.z;
            float dx1 = qx - c1.x, dy1 = qy - c1.y, dz1 = qz - c1.z;
            float dx2 = qx - c2.x, dy2 = qy - c2.y, dz2 = qz - c2.z;
            float dx3 = qx - c3.x, dy3 = qy - c3.y, dz3 = qz - c3.z;
            float d0 = fmaf(dx0, dx0, fmaf(dy0, dy0, dz0 * dz0));
            float d1 = fmaf(dx1, dx1, fmaf(dy1, dy1, dz1 * dz1));
            float d2 = fmaf(dx2, dx2, fmaf(dy2, dy2, dz2 * dz2));
            float d3 = fmaf(dx3, dx3, fmaf(dy3, dy3, dz3 * dz3));

            float dv[4] = {d0, d1, d2, d3};
#pragma unroll
            for (int u = 0; u < 4; ++u) {
                float dd = dv[u];
                if (dd < bd[KNN - 1]) {
                    int ii = base + t + u;
#pragma unroll
                    for (int j = 0; j < KNN; ++j) {
                        if (dd < bd[j]) {
                            float tf = bd[j]; bd[j] = dd; dd = tf;
                            int   ti = bi[j]; bi[j] = ii; ii = ti;
                        }
                    }
                }
            }
        }
        for (; t < cnt; ++t) {
            float4 c = s_c[t];
            float dx = qx - c.x, dy = qy - c.y, dz = qz - c.z;
            float dd = fmaf(dx, dx, fmaf(dy, dy, dz * dz));
            if (dd < bd[KNN - 1]) {
                int ii = base + t;
#pragma unroll
                for (int j = 0; j < KNN; ++j) {
                    if (dd < bd[j]) {
                        float tf = bd[j]; bd[j] = dd; dd = tf;
                        int   ti = bi[j]; bi[j] = ii; ii = ti;
                    }
                }
            }
        }
    }

    if (qi < N_POINTS) {
#pragma unroll
        for (int j = 0; j < KNN; ++j) g_knn[qi * KNN + j] = bi[j];
    }
}

// ---------------------------------------------------------------------------
// q0 = softmax(logits)
// ---------------------------------------------------------------------------
__global__ void softmax_init_kernel(const float* __restrict__ logits)
{
    const int i = blockIdx.x * blockDim.x + threadIdx.x;
    if (i >= N_POINTS) return;

    float v[NUM_CLASSES];
    const float4* lr = reinterpret_cast<const float4*>(logits + i * NUM_CLASSES);
#pragma unroll
    for (int c = 0; c < NUM_CLASSES / 4; ++c) {
        float4 x = lr[c];
        v[4 * c + 0] = x.x; v[4 * c + 1] = x.y; v[4 * c + 2] = x.z; v[4 * c + 3] = x.w;
    }
    float mx = v[0];
#pragma unroll
    for (int c = 1; c < NUM_CLASSES; ++c) mx = fmaxf(mx, v[c]);
    float s = 0.f;
#pragma unroll
    for (int c = 0; c < NUM_CLASSES; ++c) { v[c] = expf(v[c] - mx); s += v[c]; }
    const float inv = 1.f / s;
    float4* qr = reinterpret_cast<float4*>(&g_q[0][i * NUM_CLASSES]);
#pragma unroll
    for (int c = 0; c < NUM_CLASSES / 4; ++c)
        qr[c] = make_float4(v[4 * c + 0] * inv, v[4 * c + 1] * inv, v[4 * c + 2] * inv, v[4 * c + 3] * inv);
}

// ---------------------------------------------------------------------------
// One CRF iteration. If refined_out != nullptr this is the last iteration and
// we also write refined / q to global output.
// ---------------------------------------------------------------------------
__global__ void __launch_bounds__(256) crf_step_kernel(
    const float* __restrict__ logits,
    const float* __restrict__ W,            // compat_w, row-major [C][C]
    int src_buf, int dst_buf,
    float* __restrict__ refined_out,        // nullable
    float* __restrict__ q_out)              // nullable
{
    __shared__ float sW[NUM_CLASSES * NUM_CLASSES];
    for (int t = threadIdx.x; t < NUM_CLASSES * NUM_CLASSES; t += blockDim.x) sW[t] = W[t];
    __syncthreads();

    const int i = blockIdx.x * blockDim.x + threadIdx.x;
    if (i >= N_POINTS) return;

    const float* __restrict__ qsrc = g_q[src_buf];
    float msg[NUM_CLASSES];
#pragma unroll
    for (int c = 0; c < NUM_CLASSES; ++c) msg[c] = 0.f;

#pragma unroll 1
    for (int j = 0; j < KNN; ++j) {
        const int nb = g_knn[i * KNN + j];
        const float4* qr = reinterpret_cast<const float4*>(qsrc + nb * NUM_CLASSES);
#pragma unroll
        for (int c = 0; c < NUM_CLASSES / 4; ++c) {
            float4 x = qr[c];
            msg[4 * c + 0] += x.x; msg[4 * c + 1] += x.y;
            msg[4 * c + 2] += x.z; msg[4 * c + 3] += x.w;
        }
    }
#pragma unroll
    for (int c = 0; c < NUM_CLASSES; ++c) msg[c] *= (1.0f / KNN);

    float ref[NUM_CLASSES];
    {
        const float4* lr = reinterpret_cast<const float4*>(logits + i * NUM_CLASSES);
#pragma unroll
        for (int c = 0; c < NUM_CLASSES / 4; ++c) {
            float4 x = lr[c];
            ref[4 * c + 0] = x.x; ref[4 * c + 1] = x.y;
            ref[4 * c + 2] = x.z; ref[4 * c + 3] = x.w;
        }
    }
#pragma unroll
    for (int c = 0; c < NUM_CLASSES; ++c) {
        float acc = ref[c];
#pragma unroll
        for (int j = 0; j < NUM_CLASSES; ++j)
            acc = fmaf(msg[j], sW[c * NUM_CLASSES + j], acc);
        ref[c] = acc;
    }

    // softmax(ref)
    float mx = ref[0];
#pragma unroll
    for (int c = 1; c < NUM_CLASSES; ++c) mx = fmaxf(mx, ref[c]);
    float e[NUM_CLASSES];
    float s = 0.f;
#pragma unroll
    for (int c = 0; c < NUM_CLASSES; ++c) { e[c] = expf(ref[c] - mx); s += e[c]; }
    const float inv = 1.f / s;

    float4* qd = reinterpret_cast<float4*>(&g_q[dst_buf][i * NUM_CLASSES]);
#pragma unroll
    for (int c = 0; c < NUM_CLASSES / 4; ++c)
        qd[c] = make_float4(e[4 * c + 0] * inv, e[4 * c + 1] * inv, e[4 * c + 2] * inv, e[4 * c + 3] * inv);

    if (refined_out != nullptr) {
        float4* ro = reinterpret_cast<float4*>(refined_out + i * NUM_CLASSES);
        float4* qo = reinterpret_cast<float4*>(q_out + i * NUM_CLASSES);
#pragma unroll
        for (int c = 0; c < NUM_CLASSES / 4; ++c) {
            ro[c] = make_float4(ref[4 * c + 0], ref[4 * c + 1], ref[4 * c + 2], ref[4 * c + 3]);
            qo[c] = make_float4(e[4 * c + 0] * inv, e[4 * c + 1] * inv, e[4 * c + 2] * inv, e[4 * c + 3] * inv);
        }
    }
}

extern "C" void kernel_launch(void* const* d_in, const int* in_sizes, int n_in,
                              void* d_out, int out_size)
{
    const float* logits = (const float*)d_in[0];  // (20000, 20)
    const float* coords = (const float*)d_in[1];  // (20000, 3)
    const float* compat = (const float*)d_in[2];  // (20, 20)
    float* out = (float*)d_out;                   // refined (400000) then q (400000)

    (void)in_sizes; (void)n_in; (void)out_size;

    // 1) KNN graph
    knn_kernel<<<(N_POINTS + 127) / 128, 128>>>(coords);

    // 2) q = softmax(logits)
    softmax_init_kernel<<<(N_POINTS + 255) / 256, 256>>>(logits);

    // 3) 3 CRF iterations (ping-pong q buffers), last one writes outputs
    crf_step_kernel<<<(N_POINTS + 255) / 256, 256>>>(logits, compat, 0, 1, nullptr, nullptr);
    crf_step_kernel<<<(N_POINTS + 255) / 256, 256>>>(logits, compat, 1, 0, nullptr, nullptr);
    crf_step_kernel<<<(N_POINTS + 255) / 256, 256>>>(logits, compat, 0, 1,
                                                     out, out + N_POINTS * NUM_CLASSES);
}

// round 2
// speedup vs baseline: 3.1152x; 3.1152x over previous
#include <cuda_runtime.h>
#include <math.h>

#define N_POINTS    20000
#define NUM_CLASSES 20
#define KNN         16
#define NCELL_AX    16
#define NCELLS      4096
#define TILE_PTS    128
#define NT          157              /* ceil(20000/128) */
#define NPAD        (NT * TILE_PTS)  /* 20096 */

// ------------------------- device scratch (no allocs) -----------------------
__device__ int    g_counts[NCELLS];
__device__ int    g_cursor[NCELLS];
__device__ int    g_off[NCELLS];
__device__ float4 g_spts[NPAD];      // sorted points: x,y,z, orig-index-as-float-bits
__device__ float4 g_bbmin[NT];
__device__ float4 g_bbmax[NT];
__device__ int    g_knn[N_POINTS * KNN];
__device__ float  g_q[2][N_POINTS * NUM_CLASSES];

// ------------------------- morton cell id -----------------------------------
__device__ __forceinline__ unsigned part1by2(unsigned v) {
    v &= 0x3ff;
    v = (v | (v << 16)) & 0x030000FF;
    v = (v | (v << 8))  & 0x0300F00F;
    v = (v | (v << 4))  & 0x030C30C3;
    v = (v | (v << 2))  & 0x09249249;
    return v;
}
__device__ __forceinline__ int cell_of(float x, float y, float z) {
    int cx = min(NCELL_AX - 1, max(0, (int)(x * NCELL_AX)));
    int cy = min(NCELL_AX - 1, max(0, (int)(y * NCELL_AX)));
    int cz = min(NCELL_AX - 1, max(0, (int)(z * NCELL_AX)));
    return (int)(part1by2(cx) | (part1by2(cy) << 1) | (part1by2(cz) << 2));
}

// ------------------------- build kernels -------------------------------------
__global__ void clear_kernel() {
    int t = blockIdx.x * blockDim.x + threadIdx.x;
    if (t < NCELLS) { g_counts[t] = 0; g_cursor[t] = 0; }
    if (t < NPAD - N_POINTS)
        g_spts[N_POINTS + t] = make_float4(1e9f, 1e9f, 1e9f, __int_as_float(-1));
}

__global__ void hist_kernel(const float* __restrict__ coords) {
    int i = blockIdx.x * blockDim.x + threadIdx.x;
    if (i >= N_POINTS) return;
    int c = cell_of(coords[3 * i], coords[3 * i + 1], coords[3 * i + 2]);
    atomicAdd(&g_counts[c], 1);
}

__global__ void scan_kernel() {
    __shared__ int sums[256];
    int t = threadIdx.x;
    int loc[16];
    int s = 0;
#pragma unroll
    for (int j = 0; j < 16; ++j) {
        int c = g_counts[t * 16 + j];
        loc[j] = s;               // exclusive within chunk
        s += c;
    }
    sums[t] = s;
    __syncthreads();
    if (t == 0) {
        int acc = 0;
        for (int i = 0; i < 256; ++i) { int v = sums[i]; sums[i] = acc; acc += v; }
    }
    __syncthreads();
    int add = sums[t];
#pragma unroll
    for (int j = 0; j < 16; ++j) g_off[t * 16 + j] = loc[j] + add;
}

__global__ void scatter_kernel(const float* __restrict__ coords) {
    int i = blockIdx.x * blockDim.x + threadIdx.x;
    if (i >= N_POINTS) return;
    float x = coords[3 * i], y = coords[3 * i + 1], z = coords[3 * i + 2];
    int c = cell_of(x, y, z);
    int pos = g_off[c] + atomicAdd(&g_cursor[c], 1);
    g_spts[pos] = make_float4(x, y, z, __int_as_float(i));
}

__global__ void bbox_kernel() {
    int wid  = (blockIdx.x * blockDim.x + threadIdx.x) >> 5;
    int lane = threadIdx.x & 31;
    if (wid >= NT) return;
    float mnx = 1e30f, mny = 1e30f, mnz = 1e30f;
    float mxx = -1e30f, mxy = -1e30f, mxz = -1e30f;
#pragma unroll
    for (int j = 0; j < 4; ++j) {
        float4 c = g_spts[wid * TILE_PTS + lane + 32 * j];
        mnx = fminf(mnx, c.x); mny = fminf(mny, c.y); mnz = fminf(mnz, c.z);
        mxx = fmaxf(mxx, c.x); mxy = fmaxf(mxy, c.y); mxz = fmaxf(mxz, c.z);
    }
#pragma unroll
    for (int o = 16; o > 0; o >>= 1) {
        mnx = fminf(mnx, __shfl_xor_sync(0xffffffffu, mnx, o));
        mny = fminf(mny, __shfl_xor_sync(0xffffffffu, mny, o));
        mnz = fminf(mnz, __shfl_xor_sync(0xffffffffu, mnz, o));
        mxx = fmaxf(mxx, __shfl_xor_sync(0xffffffffu, mxx, o));
        mxy = fmaxf(mxy, __shfl_xor_sync(0xffffffffu, mxy, o));
        mxz = fmaxf(mxz, __shfl_xor_sync(0xffffffffu, mxz, o));
    }
    if (lane == 0) {
        g_bbmin[wid] = make_float4(mnx, mny, mnz, 0.f);
        g_bbmax[wid] = make_float4(mxx, mxy, mxz, 0.f);
    }
}

// ------------------------- KNN with tile pruning -----------------------------
#define TRY_INSERT(DD, II)                                              \
    do {                                                                \
        float _d = (DD); int _i = (II);                                 \
        if (_d < bd[KNN - 1]) {                                         \
            _Pragma("unroll")                                           \
            for (int _j = 0; _j < KNN; ++_j) {                          \
                if (_d < bd[_j]) {                                      \
                    float _tf = bd[_j]; bd[_j] = _d; _d = _tf;          \
                    int   _ti = bi[_j]; bi[_j] = _i; _i = _ti;          \
                }                                                       \
            }                                                           \
        }                                                               \
    } while (0)

__global__ void __launch_bounds__(TILE_PTS) knn_kernel()
{
    const int pos   = blockIdx.x * TILE_PTS + threadIdx.x; // sorted position
    const bool valid = (pos < N_POINTS);
    float4 me = valid ? g_spts[pos] : make_float4(2e9f, 2e9f, 2e9f, 0.f);
    const float qx = me.x, qy = me.y, qz = me.z;
    const int qorig = __float_as_int(me.w);
    const int t0 = blockIdx.x; // block b == tile b (uniform per warp)

    float bd[KNN];
    int   bi[KNN];
#pragma unroll
    for (int j = 0; j < KNN; ++j) { bd[j] = 3.4e38f; bi[j] = -1; }

    // sweep tiles outward from own tile: t0, t0-1, t0+1, t0-2, ...
    for (int s = 0; s < 2 * NT - 1; ++s) {
        const int d = (s + 1) >> 1;
        const int t = (s & 1) ? (t0 - d) : (t0 + d);
        if (t < 0 || t >= NT) continue;

        // AABB lower-bound distance for this lane's query
        float4 bmn = g_bbmin[t];
        float4 bmx = g_bbmax[t];
        float dx = fmaxf(fmaxf(bmn.x - qx, qx - bmx.x), 0.f);
        float dy = fmaxf(fmaxf(bmn.y - qy, qy - bmx.y), 0.f);
        float dz = fmaxf(fmaxf(bmn.z - qz, qz - bmx.z), 0.f);
        float dmin2 = dx * dx + dy * dy + dz * dz;
        bool need = valid && (dmin2 <= bd[KNN - 1]);
        if (__ballot_sync(0xffffffffu, need) == 0u) continue;

        const float4* __restrict__ tp = g_spts + t * TILE_PTS;
#pragma unroll 1
        for (int i = 0; i < TILE_PTS; i += 4) {
            float4 c0 = tp[i + 0];
            float4 c1 = tp[i + 1];
            float4 c2 = tp[i + 2];
            float4 c3 = tp[i + 3];
            float dx0 = qx - c0.x, dy0 = qy - c0.y, dz0 = qz - c0.z;
            float dx1 = qx - c1.x, dy1 = qy - c1.y, dz1 = qz - c1.z;
            float dx2 = qx - c2.x, dy2 = qy - c2.y, dz2 = qz - c2.z;
            float dx3 = qx - c3.x, dy3 = qy - c3.y, dz3 = qz - c3.z;
            float d0 = fmaf(dx0, dx0, fmaf(dy0, dy0, dz0 * dz0));
            float d1 = fmaf(dx1, dx1, fmaf(dy1, dy1, dz1 * dz1));
            float d2 = fmaf(dx2, dx2, fmaf(dy2, dy2, dz2 * dz2));
            float d3 = fmaf(dx3, dx3, fmaf(dy3, dy3, dz3 * dz3));
            TRY_INSERT(d0, __float_as_int(c0.w));
            TRY_INSERT(d1, __float_as_int(c1.w));
            TRY_INSERT(d2, __float_as_int(c2.w));
            TRY_INSERT(d3, __float_as_int(c3.w));
        }
    }

    if (valid) {
#pragma unroll
        for (int j = 0; j < KNN; ++j) g_knn[qorig * KNN + j] = bi[j];
    }
}

// ------------------------- softmax init --------------------------------------
__global__ void softmax_init_kernel(const float* __restrict__ logits)
{
    const int i = blockIdx.x * blockDim.x + threadIdx.x;
    if (i >= N_POINTS) return;
    float v[NUM_CLASSES];
    const float4* lr = reinterpret_cast<const float4*>(logits + i * NUM_CLASSES);
#pragma unroll
    for (int c = 0; c < NUM_CLASSES / 4; ++c) {
        float4 x = lr[c];
        v[4*c+0] = x.x; v[4*c+1] = x.y; v[4*c+2] = x.z; v[4*c+3] = x.w;
    }
    float mx = v[0];
#pragma unroll
    for (int c = 1; c < NUM_CLASSES; ++c) mx = fmaxf(mx, v[c]);
    float s = 0.f;
#pragma unroll
    for (int c = 0; c < NUM_CLASSES; ++c) { v[c] = __expf(v[c] - mx); s += v[c]; }
    const float inv = 1.f / s;
    float4* qr = reinterpret_cast<float4*>(&g_q[0][i * NUM_CLASSES]);
#pragma unroll
    for (int c = 0; c < NUM_CLASSES / 4; ++c)
        qr[c] = make_float4(v[4*c+0]*inv, v[4*c+1]*inv, v[4*c+2]*inv, v[4*c+3]*inv);
}

// ------------------------- CRF step -------------------------------------------
__global__ void crf_step_kernel(
    const float* __restrict__ logits,
    const float* __restrict__ W,
    int src_buf, int dst_buf,
    float* __restrict__ refined_out,
    float* __restrict__ q_out)
{
    __shared__ float sW[NUM_CLASSES * NUM_CLASSES];
    for (int t = threadIdx.x; t < NUM_CLASSES * NUM_CLASSES; t += blockDim.x) sW[t] = W[t];
    __syncthreads();

    const int i = blockIdx.x * blockDim.x + threadIdx.x;
    if (i >= N_POINTS) return;

    const float* __restrict__ qsrc = g_q[src_buf];

    // load all 16 neighbour indices up-front (4x int4) for MLP
    const int4* kr = reinterpret_cast<const int4*>(&g_knn[i * KNN]);
    int4 k0 = kr[0], k1 = kr[1], k2 = kr[2], k3 = kr[3];

    float msg[NUM_CLASSES];
#pragma unroll
    for (int c = 0; c < NUM_CLASSES; ++c) msg[c] = 0.f;

#define GATHER(NB)                                                          \
    do {                                                                    \
        const float4* qr = reinterpret_cast<const float4*>(qsrc + (NB) * NUM_CLASSES); \
        float4 a0 = qr[0], a1 = qr[1], a2 = qr[2], a3 = qr[3], a4 = qr[4];  \
        msg[0]+=a0.x; msg[1]+=a0.y; msg[2]+=a0.z; msg[3]+=a0.w;             \
        msg[4]+=a1.x; msg[5]+=a1.y; msg[6]+=a1.z; msg[7]+=a1.w;             \
        msg[8]+=a2.x; msg[9]+=a2.y; msg[10]+=a2.z; msg[11]+=a2.w;           \
        msg[12]+=a3.x; msg[13]+=a3.y; msg[14]+=a3.z; msg[15]+=a3.w;         \
        msg[16]+=a4.x; msg[17]+=a4.y; msg[18]+=a4.z; msg[19]+=a4.w;         \
    } while (0)

    GATHER(k0.x); GATHER(k0.y); GATHER(k0.z); GATHER(k0.w);
    GATHER(k1.x); GATHER(k1.y); GATHER(k1.z); GATHER(k1.w);
    GATHER(k2.x); GATHER(k2.y); GATHER(k2.z); GATHER(k2.w);
    GATHER(k3.x); GATHER(k3.y); GATHER(k3.z); GATHER(k3.w);
#undef GATHER

#pragma unroll
    for (int c = 0; c < NUM_CLASSES; ++c) msg[c] *= (1.0f / KNN);

    float ref[NUM_CLASSES];
    {
        const float4* lr = reinterpret_cast<const float4*>(logits + i * NUM_CLASSES);
#pragma unroll
        for (int c = 0; c < NUM_CLASSES / 4; ++c) {
            float4 x = lr[c];
            ref[4*c+0] = x.x; ref[4*c+1] = x.y; ref[4*c+2] = x.z; ref[4*c+3] = x.w;
        }
    }
#pragma unroll
    for (int c = 0; c < NUM_CLASSES; ++c) {
        float acc = ref[c];
#pragma unroll
        for (int j = 0; j < NUM_CLASSES; ++j)
            acc = fmaf(msg[j], sW[c * NUM_CLASSES + j], acc);
        ref[c] = acc;
    }

    float mx = ref[0];
#pragma unroll
    for (int c = 1; c < NUM_CLASSES; ++c) mx = fmaxf(mx, ref[c]);
    float e[NUM_CLASSES];
    float s = 0.f;
#pragma unroll
    for (int c = 0; c < NUM_CLASSES; ++c) { e[c] = __expf(ref[c] - mx); s += e[c]; }
    const float inv = 1.f / s;

    float4* qd = reinterpret_cast<float4*>(&g_q[dst_buf][i * NUM_CLASSES]);
#pragma unroll
    for (int c = 0; c < NUM_CLASSES / 4; ++c)
        qd[c] = make_float4(e[4*c+0]*inv, e[4*c+1]*inv, e[4*c+2]*inv, e[4*c+3]*inv);

    if (refined_out != nullptr) {
        float4* ro = reinterpret_cast<float4*>(refined_out + i * NUM_CLASSES);
        float4* qo = reinterpret_cast<float4*>(q_out + i * NUM_CLASSES);
#pragma unroll
        for (int c = 0; c < NUM_CLASSES / 4; ++c) {
            ro[c] = make_float4(ref[4*c+0], ref[4*c+1], ref[4*c+2], ref[4*c+3]);
            qo[c] = make_float4(e[4*c+0]*inv, e[4*c+1]*inv, e[4*c+2]*inv, e[4*c+3]*inv);
        }
    }
}

// ------------------------- launch ---------------------------------------------
extern "C" void kernel_launch(void* const* d_in, const int* in_sizes, int n_in,
                              void* d_out, int out_size)
{
    const float* logits = (const float*)d_in[0];  // (20000, 20)
    const float* coords = (const float*)d_in[1];  // (20000, 3)
    const float* compat = (const float*)d_in[2];  // (20, 20)
    float* out = (float*)d_out;                   // refined (400000) then q (400000)
    (void)in_sizes; (void)n_in; (void)out_size;

    // spatial sort (counting sort by morton cell)
    clear_kernel<<<(NCELLS + 255) / 256, 256>>>();
    hist_kernel<<<(N_POINTS + 255) / 256, 256>>>(coords);
    scan_kernel<<<1, 256>>>();
    scatter_kernel<<<(N_POINTS + 255) / 256, 256>>>(coords);
    bbox_kernel<<<(NT * 32 + 127) / 128, 128>>>();

    // pruned exact KNN
    knn_kernel<<<NT, TILE_PTS>>>();

    // CRF
    softmax_init_kernel<<<(N_POINTS + 255) / 256, 256>>>(logits);
    crf_step_kernel<<<(N_POINTS + 255) / 256, 256>>>(logits, compat, 0, 1, nullptr, nullptr);
    crf_step_kernel<<<(N_POINTS + 255) / 256, 256>>>(logits, compat, 1, 0, nullptr, nullptr);
    crf_step_kernel<<<(N_POINTS + 255) / 256, 256>>>(logits, compat, 0, 1,
                                                     out, out + N_POINTS * NUM_CLASSES);
}

// round 3
// speedup vs baseline: 3.4104x; 1.0947x over previous
#include <cuda_runtime.h>
#include <math.h>

#define N_POINTS    20000
#define NUM_CLASSES 20
#define KNN         16
#define NCELL_AX    16
#define NCELLS      4096
#define TILE_PTS    128
#define NT          157              /* ceil(20000/128) */
#define NPAD        (NT * TILE_PTS)  /* 20096 */
#define NSPLIT      4

// ------------------------- device scratch (no allocs) -----------------------
__device__ int    g_counts[NCELLS];
__device__ int    g_cursor[NCELLS];
__device__ int    g_off[NCELLS];
__device__ float4 g_spts[NPAD];      // sorted points: x,y,z, orig-index bits
__device__ float4 g_bbmin[NT];
__device__ float4 g_bbmax[NT];
__device__ float2 g_cand[NSPLIT][N_POINTS * KNN];  // per-split (d2, idx bits), by sorted pos
__device__ int    g_knn[N_POINTS * KNN];
__device__ float  g_q[2][N_POINTS * NUM_CLASSES];

// ------------------------- morton cell id -----------------------------------
__device__ __forceinline__ unsigned part1by2(unsigned v) {
    v &= 0x3ff;
    v = (v | (v << 16)) & 0x030000FF;
    v = (v | (v << 8))  & 0x0300F00F;
    v = (v | (v << 4))  & 0x030C30C3;
    v = (v | (v << 2))  & 0x09249249;
    return v;
}
__device__ __forceinline__ int cell_of(float x, float y, float z) {
    int cx = min(NCELL_AX - 1, max(0, (int)(x * NCELL_AX)));
    int cy = min(NCELL_AX - 1, max(0, (int)(y * NCELL_AX)));
    int cz = min(NCELL_AX - 1, max(0, (int)(z * NCELL_AX)));
    return (int)(part1by2(cx) | (part1by2(cy) << 1) | (part1by2(cz) << 2));
}

// ------------------------- build kernels -------------------------------------
__global__ void clear_kernel() {
    int t = blockIdx.x * blockDim.x + threadIdx.x;
    if (t < NCELLS) { g_counts[t] = 0; g_cursor[t] = 0; }
    if (t < NPAD - N_POINTS)
        g_spts[N_POINTS + t] = make_float4(1e9f, 1e9f, 1e9f, __int_as_float(-1));
}

__global__ void hist_kernel(const float* __restrict__ coords) {
    int i = blockIdx.x * blockDim.x + threadIdx.x;
    if (i >= N_POINTS) return;
    int c = cell_of(coords[3 * i], coords[3 * i + 1], coords[3 * i + 2]);
    atomicAdd(&g_counts[c], 1);
}

__global__ void scan_kernel() {
    __shared__ int sums[256];
    int t = threadIdx.x;
    int loc[16];
    int s = 0;
#pragma unroll
    for (int j = 0; j < 16; ++j) {
        int c = g_counts[t * 16 + j];
        loc[j] = s;
        s += c;
    }
    sums[t] = s;
    __syncthreads();
    if (t == 0) {
        int acc = 0;
        for (int i = 0; i < 256; ++i) { int v = sums[i]; sums[i] = acc; acc += v; }
    }
    __syncthreads();
    int add = sums[t];
#pragma unroll
    for (int j = 0; j < 16; ++j) g_off[t * 16 + j] = loc[j] + add;
}

__global__ void scatter_kernel(const float* __restrict__ coords) {
    int i = blockIdx.x * blockDim.x + threadIdx.x;
    if (i >= N_POINTS) return;
    float x = coords[3 * i], y = coords[3 * i + 1], z = coords[3 * i + 2];
    int c = cell_of(x, y, z);
    int pos = g_off[c] + atomicAdd(&g_cursor[c], 1);
    g_spts[pos] = make_float4(x, y, z, __int_as_float(i));
}

__global__ void bbox_kernel() {
    int wid  = (blockIdx.x * blockDim.x + threadIdx.x) >> 5;
    int lane = threadIdx.x & 31;
    if (wid >= NT) return;
    float mnx = 1e30f, mny = 1e30f, mnz = 1e30f;
    float mxx = -1e30f, mxy = -1e30f, mxz = -1e30f;
#pragma unroll
    for (int j = 0; j < 4; ++j) {
        float4 c = g_spts[wid * TILE_PTS + lane + 32 * j];
        if (c.x < 1e8f) {   // skip pads for tighter last-tile box
            mnx = fminf(mnx, c.x); mny = fminf(mny, c.y); mnz = fminf(mnz, c.z);
            mxx = fmaxf(mxx, c.x); mxy = fmaxf(mxy, c.y); mxz = fmaxf(mxz, c.z);
        }
    }
#pragma unroll
    for (int o = 16; o > 0; o >>= 1) {
        mnx = fminf(mnx, __shfl_xor_sync(0xffffffffu, mnx, o));
        mny = fminf(mny, __shfl_xor_sync(0xffffffffu, mny, o));
        mnz = fminf(mnz, __shfl_xor_sync(0xffffffffu, mnz, o));
        mxx = fmaxf(mxx, __shfl_xor_sync(0xffffffffu, mxx, o));
        mxy = fmaxf(mxy, __shfl_xor_sync(0xffffffffu, mxy, o));
        mxz = fmaxf(mxz, __shfl_xor_sync(0xffffffffu, mxz, o));
    }
    if (lane == 0) {
        g_bbmin[wid] = make_float4(mnx, mny, mnz, 0.f);
        g_bbmax[wid] = make_float4(mxx, mxy, mxz, 0.f);
    }
}

// ------------------------- split KNN with tile pruning -----------------------
#define TRY_INSERT(DD, II)                                              \
    do {                                                                \
        float _d = (DD); int _i = (II);                                 \
        if (_d < bd[KNN - 1]) {                                         \
            _Pragma("unroll")                                           \
            for (int _j = 0; _j < KNN; ++_j) {                          \
                if (_d < bd[_j]) {                                      \
                    float _tf = bd[_j]; bd[_j] = _d; _d = _tf;          \
                    int   _ti = bi[_j]; bi[_j] = _i; _i = _ti;          \
                }                                                       \
            }                                                           \
        }                                                               \
    } while (0)

__global__ void __launch_bounds__(TILE_PTS) knn_split_kernel()
{
    const int split = blockIdx.y;
    const int t0    = blockIdx.x;
    const int pos   = t0 * TILE_PTS + threadIdx.x;
    const bool valid = (pos < N_POINTS);
    float4 me = g_spts[pos];          // pads are (1e9,...) -> never "need"
    const float qx = me.x, qy = me.y, qz = me.z;

    float bd[KNN];
    int   bi[KNN];
#pragma unroll
    for (int j = 0; j < KNN; ++j) { bd[j] = 3.4e38f; bi[j] = -1; }

    // outward sweep, strided by NSPLIT: split k takes steps k, k+4, k+8, ...
    for (int s = split; s < 2 * NT - 1; s += NSPLIT) {
        const int d = (s + 1) >> 1;
        const int t = (s & 1) ? (t0 - d) : (t0 + d);
        if ((unsigned)t >= (unsigned)NT) continue;

        float4 bmn = g_bbmin[t];
        float4 bmx = g_bbmax[t];
        float dx = fmaxf(fmaxf(bmn.x - qx, qx - bmx.x), 0.f);
        float dy = fmaxf(fmaxf(bmn.y - qy, qy - bmx.y), 0.f);
        float dz = fmaxf(fmaxf(bmn.z - qz, qz - bmx.z), 0.f);
        float dmin2 = dx * dx + dy * dy + dz * dz;
        bool need = valid && (dmin2 <= bd[KNN - 1]);
        if (__ballot_sync(0xffffffffu, need) == 0u) continue;

        const float4* __restrict__ tp = g_spts + t * TILE_PTS;
#pragma unroll 1
        for (int i = 0; i < TILE_PTS; i += 8) {
            float4 c[8];
#pragma unroll
            for (int u = 0; u < 8; ++u) c[u] = tp[i + u];
            float dd[8];
#pragma unroll
            for (int u = 0; u < 8; ++u) {
                float ddx = qx - c[u].x, ddy = qy - c[u].y, ddz = qz - c[u].z;
                dd[u] = fmaf(ddx, ddx, fmaf(ddy, ddy, ddz * ddz));
            }
#pragma unroll
            for (int u = 0; u < 8; ++u) TRY_INSERT(dd[u], __float_as_int(c[u].w));
        }
    }

    if (valid) {
        float2* o = &g_cand[split][pos * KNN];
#pragma unroll
        for (int j = 0; j < KNN; ++j)
            o[j] = make_float2(bd[j], __int_as_float(bi[j]));
    }
}

// 4-way merge of per-split sorted lists -> final 16 neighbor indices
__global__ void knn_merge_kernel()
{
    const int pos = blockIdx.x * blockDim.x + threadIdx.x;
    if (pos >= N_POINTS) return;
    const int orig = __float_as_int(g_spts[pos].w);

    const float2* c0 = &g_cand[0][pos * KNN];
    const float2* c1 = &g_cand[1][pos * KNN];
    const float2* c2 = &g_cand[2][pos * KNN];
    const float2* c3 = &g_cand[3][pos * KNN];
    int h0 = 0, h1 = 0, h2 = 0, h3 = 0;
    float2 v0 = c0[0], v1 = c1[0], v2 = c2[0], v3 = c3[0];

#pragma unroll
    for (int j = 0; j < KNN; ++j) {
        int pick;
        if (v0.x <= v1.x && v0.x <= v2.x && v0.x <= v3.x)      pick = __float_as_int(v0.y);
        else if (v1.x <= v2.x && v1.x <= v3.x)                 pick = __float_as_int(v1.y);
        else if (v2.x <= v3.x)                                 pick = __float_as_int(v2.y);
        else                                                   pick = __float_as_int(v3.y);
        g_knn[orig * KNN + j] = pick;
        if (v0.x <= v1.x && v0.x <= v2.x && v0.x <= v3.x)      v0 = (++h0 < KNN) ? c0[h0] : make_float2(3.4e38f, 0.f);
        else if (v1.x <= v2.x && v1.x <= v3.x)                 v1 = (++h1 < KNN) ? c1[h1] : make_float2(3.4e38f, 0.f);
        else if (v2.x <= v3.x)                                 v2 = (++h2 < KNN) ? c2[h2] : make_float2(3.4e38f, 0.f);
        else                                                   v3 = (++h3 < KNN) ? c3[h3] : make_float2(3.4e38f, 0.f);
    }
}

// ------------------------- softmax init --------------------------------------
__global__ void softmax_init_kernel(const float* __restrict__ logits)
{
    const int i = blockIdx.x * blockDim.x + threadIdx.x;
    if (i >= N_POINTS) return;
    float v[NUM_CLASSES];
    const float4* lr = reinterpret_cast<const float4*>(logits + i * NUM_CLASSES);
#pragma unroll
    for (int c = 0; c < NUM_CLASSES / 4; ++c) {
        float4 x = lr[c];
        v[4*c+0] = x.x; v[4*c+1] = x.y; v[4*c+2] = x.z; v[4*c+3] = x.w;
    }
    float mx = v[0];
#pragma unroll
    for (int c = 1; c < NUM_CLASSES; ++c) mx = fmaxf(mx, v[c]);
    float s = 0.f;
#pragma unroll
    for (int c = 0; c < NUM_CLASSES; ++c) { v[c] = __expf(v[c] - mx); s += v[c]; }
    const float inv = 1.f / s;
    float4* qr = reinterpret_cast<float4*>(&g_q[0][i * NUM_CLASSES]);
#pragma unroll
    for (int c = 0; c < NUM_CLASSES / 4; ++c)
        qr[c] = make_float4(v[4*c+0]*inv, v[4*c+1]*inv, v[4*c+2]*inv, v[4*c+3]*inv);
}

// ------------------------- CRF step: 2 threads per point ----------------------
// sub = g & 1 handles classes [sub*10, sub*10+10). Partner exchange via shfl_xor(1).
__global__ void __launch_bounds__(256) crf_step_kernel(
    const float* __restrict__ logits,
    const float* __restrict__ W,
    int src_buf, int dst_buf,
    float* __restrict__ refined_out,
    float* __restrict__ q_out)
{
    __shared__ float sW[NUM_CLASSES * NUM_CLASSES];
    for (int t = threadIdx.x; t < NUM_CLASSES * NUM_CLASSES; t += blockDim.x) sW[t] = W[t];
    __syncthreads();

    const int g = blockIdx.x * blockDim.x + threadIdx.x;
    const int i = g >> 1;
    const int sub = g & 1;
    if (i >= N_POINTS) return;

    const float* __restrict__ qsrc = g_q[src_buf];

    const int4* kr = reinterpret_cast<const int4*>(&g_knn[i * KNN]);
    int4 k0 = kr[0], k1 = kr[1], k2 = kr[2], k3 = kr[3];
    int nb[KNN] = {k0.x, k0.y, k0.z, k0.w, k1.x, k1.y, k1.z, k1.w,
                   k2.x, k2.y, k2.z, k2.w, k3.x, k3.y, k3.z, k3.w};

    const int half = 10;
    float msg[half];
#pragma unroll
    for (int c = 0; c < half; ++c) msg[c] = 0.f;

#pragma unroll
    for (int j = 0; j < KNN; ++j) {
        const float2* qr = reinterpret_cast<const float2*>(qsrc + nb[j] * NUM_CLASSES + sub * half);
#pragma unroll
        for (int c = 0; c < half / 2; ++c) {
            float2 x = qr[c];
            msg[2*c+0] += x.x; msg[2*c+1] += x.y;
        }
    }
#pragma unroll
    for (int c = 0; c < half; ++c) msg[c] *= (1.0f / KNN);

    // assemble full msg vector: my half + partner half (static indices only)
    float mall[NUM_CLASSES];
#pragma unroll
    for (int c = 0; c < half; ++c) {
        float other = __shfl_xor_sync(0xffffffffu, msg[c], 1);
        mall[c]        = sub ? other  : msg[c];
        mall[half + c] = sub ? msg[c] : other;
    }

    // refined for my half
    float ref[half];
    {
        const float2* lr = reinterpret_cast<const float2*>(logits + i * NUM_CLASSES + sub * half);
#pragma unroll
        for (int c = 0; c < half / 2; ++c) {
            float2 x = lr[c];
            ref[2*c+0] = x.x; ref[2*c+1] = x.y;
        }
    }
    const int c0 = sub * half;
#pragma unroll
    for (int c = 0; c < half; ++c) {
        float acc = ref[c];
#pragma unroll
        for (int j = 0; j < NUM_CLASSES; ++j)
            acc = fmaf(mall[j], sW[(c0 + c) * NUM_CLASSES + j], acc);
        ref[c] = acc;
    }

    // softmax across pair
    float mx = ref[0];
#pragma unroll
    for (int c = 1; c < half; ++c) mx = fmaxf(mx, ref[c]);
    mx = fmaxf(mx, __shfl_xor_sync(0xffffffffu, mx, 1));
    float e[half];
    float s = 0.f;
#pragma unroll
    for (int c = 0; c < half; ++c) { e[c] = __expf(ref[c] - mx); s += e[c]; }
    s += __shfl_xor_sync(0xffffffffu, s, 1);
    const float inv = 1.f / s;

    float2* qd = reinterpret_cast<float2*>(&g_q[dst_buf][i * NUM_CLASSES + sub * half]);
#pragma unroll
    for (int c = 0; c < half / 2; ++c)
        qd[c] = make_float2(e[2*c+0] * inv, e[2*c+1] * inv);

    if (refined_out != nullptr) {
        float2* ro = reinterpret_cast<float2*>(refined_out + i * NUM_CLASSES + sub * half);
        float2* qo = reinterpret_cast<float2*>(q_out + i * NUM_CLASSES + sub * half);
#pragma unroll
        for (int c = 0; c < half / 2; ++c) {
            ro[c] = make_float2(ref[2*c+0], ref[2*c+1]);
            qo[c] = make_float2(e[2*c+0] * inv, e[2*c+1] * inv);
        }
    }
}

// ------------------------- launch ---------------------------------------------
extern "C" void kernel_launch(void* const* d_in, const int* in_sizes, int n_in,
                              void* d_out, int out_size)
{
    const float* logits = (const float*)d_in[0];  // (20000, 20)
    const float* coords = (const float*)d_in[1];  // (20000, 3)
    const float* compat = (const float*)d_in[2];  // (20, 20)
    float* out = (float*)d_out;                   // refined (400000) then q (400000)
    (void)in_sizes; (void)n_in; (void)out_size;

    // spatial counting sort by morton cell
    clear_kernel<<<(NCELLS + 255) / 256, 256>>>();
    hist_kernel<<<(N_POINTS + 255) / 256, 256>>>(coords);
    scan_kernel<<<1, 256>>>();
    scatter_kernel<<<(N_POINTS + 255) / 256, 256>>>(coords);
    bbox_kernel<<<(NT * 32 + 127) / 128, 128>>>();

    // pruned exact KNN, 4-way split sweep + merge
    dim3 kg(NT, NSPLIT);
    knn_split_kernel<<<kg, TILE_PTS>>>();
    knn_merge_kernel<<<(N_POINTS + 255) / 256, 256>>>();

    // CRF (2 threads per point)
    softmax_init_kernel<<<(N_POINTS + 255) / 256, 256>>>(logits);
    const int crf_threads = 2 * N_POINTS;
    crf_step_kernel<<<(crf_threads + 255) / 256, 256>>>(logits, compat, 0, 1, nullptr, nullptr);
    crf_step_kernel<<<(crf_threads + 255) / 256, 256>>>(logits, compat, 1, 0, nullptr, nullptr);
    crf_step_kernel<<<(crf_threads + 255) / 256, 256>>>(logits, compat, 0, 1,
                                                        out, out + N_POINTS * NUM_CLASSES);
}

// round 4
// speedup vs baseline: 3.7751x; 1.1070x over previous
#include <cuda_runtime.h>
#include <math.h>

#define N_POINTS    20000
#define NUM_CLASSES 20
#define KNN         16
#define NCELL_AX    16
#define NCELLS      4096
#define TILE_PTS    128
#define NT          157              /* ceil(20000/128) */
#define NPAD        (NT * TILE_PTS)  /* 20096 */
#define NSPB        3                /* pass-B splits */

// ------------------------- device scratch (no allocs) -----------------------
__device__ int    g_counts[NCELLS];
__device__ int    g_cursor[NCELLS];
__device__ int    g_off[NCELLS];
__device__ float4 g_spts[NPAD];      // sorted points: x,y,z, orig-index bits
__device__ float4 g_bbmin[NT];
__device__ float4 g_bbmax[NT];
__device__ float  g_r2[NPAD];        // per-query radius bound (0 for pads)
__device__ float  g_r2max[NT];       // per-tile max radius
__device__ int    g_tlist[NT * NT];  // candidate tiles per tile
__device__ int    g_tcnt[NT];
__device__ float2 g_cand[1 + NSPB][N_POINTS * KNN]; // (d2, pos bits) lists
__device__ int    g_knn[N_POINTS * KNN];            // neighbor SORTED positions
__device__ float  g_logits_s[N_POINTS * NUM_CLASSES]; // logits in sorted order
__device__ float  g_q[2][N_POINTS * NUM_CLASSES];     // q in sorted order

// ------------------------- morton cell id -----------------------------------
__device__ __forceinline__ unsigned part1by2(unsigned v) {
    v &= 0x3ff;
    v = (v | (v << 16)) & 0x030000FF;
    v = (v | (v << 8))  & 0x0300F00F;
    v = (v | (v << 4))  & 0x030C30C3;
    v = (v | (v << 2))  & 0x09249249;
    return v;
}
__device__ __forceinline__ int cell_of(float x, float y, float z) {
    int cx = min(NCELL_AX - 1, max(0, (int)(x * NCELL_AX)));
    int cy = min(NCELL_AX - 1, max(0, (int)(y * NCELL_AX)));
    int cz = min(NCELL_AX - 1, max(0, (int)(z * NCELL_AX)));
    return (int)(part1by2(cx) | (part1by2(cy) << 1) | (part1by2(cz) << 2));
}

// ------------------------- build kernels -------------------------------------
__global__ void clear_kernel() {
    int t = blockIdx.x * blockDim.x + threadIdx.x;
    if (t < NCELLS) { g_counts[t] = 0; g_cursor[t] = 0; }
    if (t < NT) g_tcnt[t] = 0;
    if (t < NPAD - N_POINTS)
        g_spts[N_POINTS + t] = make_float4(1e9f, 1e9f, 1e9f, __int_as_float(-1));
}

__global__ void hist_kernel(const float* __restrict__ coords) {
    int i = blockIdx.x * blockDim.x + threadIdx.x;
    if (i >= N_POINTS) return;
    int c = cell_of(coords[3 * i], coords[3 * i + 1], coords[3 * i + 2]);
    atomicAdd(&g_counts[c], 1);
}

__global__ void scan_kernel() {
    __shared__ int sums[256];
    int t = threadIdx.x;
    int loc[16];
    int s = 0;
#pragma unroll
    for (int j = 0; j < 16; ++j) {
        int c = g_counts[t * 16 + j];
        loc[j] = s;
        s += c;
    }
    sums[t] = s;
    __syncthreads();
    if (t == 0) {
        int acc = 0;
        for (int i = 0; i < 256; ++i) { int v = sums[i]; sums[i] = acc; acc += v; }
    }
    __syncthreads();
    int add = sums[t];
#pragma unroll
    for (int j = 0; j < 16; ++j) g_off[t * 16 + j] = loc[j] + add;
}

__global__ void scatter_kernel(const float* __restrict__ coords) {
    int i = blockIdx.x * blockDim.x + threadIdx.x;
    if (i >= N_POINTS) return;
    float x = coords[3 * i], y = coords[3 * i + 1], z = coords[3 * i + 2];
    int c = cell_of(x, y, z);
    int pos = g_off[c] + atomicAdd(&g_cursor[c], 1);
    g_spts[pos] = make_float4(x, y, z, __int_as_float(i));
}

__global__ void bbox_kernel() {
    int wid  = (blockIdx.x * blockDim.x + threadIdx.x) >> 5;
    int lane = threadIdx.x & 31;
    if (wid >= NT) return;
    float mnx = 1e30f, mny = 1e30f, mnz = 1e30f;
    float mxx = -1e30f, mxy = -1e30f, mxz = -1e30f;
#pragma unroll
    for (int j = 0; j < 4; ++j) {
        float4 c = g_spts[wid * TILE_PTS + lane + 32 * j];
        if (c.x < 1e8f) {
            mnx = fminf(mnx, c.x); mny = fminf(mny, c.y); mnz = fminf(mnz, c.z);
            mxx = fmaxf(mxx, c.x); mxy = fmaxf(mxy, c.y); mxz = fmaxf(mxz, c.z);
        }
    }
#pragma unroll
    for (int o = 16; o > 0; o >>= 1) {
        mnx = fminf(mnx, __shfl_xor_sync(0xffffffffu, mnx, o));
        mny = fminf(mny, __shfl_xor_sync(0xffffffffu, mny, o));
        mnz = fminf(mnz, __shfl_xor_sync(0xffffffffu, mnz, o));
        mxx = fmaxf(mxx, __shfl_xor_sync(0xffffffffu, mxx, o));
        mxy = fmaxf(mxy, __shfl_xor_sync(0xffffffffu, mxy, o));
        mxz = fmaxf(mxz, __shfl_xor_sync(0xffffffffu, mxz, o));
    }
    if (lane == 0) {
        g_bbmin[wid] = make_float4(mnx, mny, mnz, 0.f);
        g_bbmax[wid] = make_float4(mxx, mxy, mxz, 0.f);
    }
}

// ------------------------- insertion macros -----------------------------------
#define TRY_INSERT(DD, II)                                              \
    do {                                                                \
        float _d = (DD); int _i = (II);                                 \
        if (_d < bd[KNN - 1]) {                                         \
            _Pragma("unroll")                                           \
            for (int _j = 0; _j < KNN; ++_j) {                          \
                if (_d < bd[_j]) {                                      \
                    float _tf = bd[_j]; bd[_j] = _d; _d = _tf;          \
                    int   _ti = bi[_j]; bi[_j] = _i; _i = _ti;          \
                }                                                       \
            }                                                           \
        }                                                               \
    } while (0)

#define TRY_INSERT_R(DD, II)                                            \
    do {                                                                \
        float _d = (DD); int _i = (II);                                 \
        if (_d <= r2 && _d < bd[KNN - 1]) {                             \
            _Pragma("unroll")                                           \
            for (int _j = 0; _j < KNN; ++_j) {                          \
                if (_d < bd[_j]) {                                      \
                    float _tf = bd[_j]; bd[_j] = _d; _d = _tf;          \
                    int   _ti = bi[_j]; bi[_j] = _i; _i = _ti;          \
                }                                                       \
            }                                                           \
        }                                                               \
    } while (0)

// ------------------------- pass A: own-tile top-16 + radius ------------------
__global__ void __launch_bounds__(TILE_PTS) knn_own_kernel()
{
    __shared__ float s_r2w[TILE_PTS / 32];
    const int t0  = blockIdx.x;
    const int pos = t0 * TILE_PTS + threadIdx.x;
    const bool valid = (pos < N_POINTS);
    float4 me = g_spts[pos];
    const float qx = me.x, qy = me.y, qz = me.z;

    float bd[KNN];
    int   bi[KNN];
#pragma unroll
    for (int j = 0; j < KNN; ++j) { bd[j] = 3.4e38f; bi[j] = -1; }

    const float4* __restrict__ tp = g_spts + t0 * TILE_PTS;
#pragma unroll 1
    for (int i = 0; i < TILE_PTS; i += 8) {
        float4 c[8];
#pragma unroll
        for (int u = 0; u < 8; ++u) c[u] = tp[i + u];
        float dd[8];
#pragma unroll
        for (int u = 0; u < 8; ++u) {
            float ddx = qx - c[u].x, ddy = qy - c[u].y, ddz = qz - c[u].z;
            dd[u] = fmaf(ddx, ddx, fmaf(ddy, ddy, ddz * ddz));
        }
#pragma unroll
        for (int u = 0; u < 8; ++u) TRY_INSERT(dd[u], t0 * TILE_PTS + i + u);
    }

    const float r2lane = valid ? bd[KNN - 1] : 0.f;
    // block max of r2
    float m = r2lane;
#pragma unroll
    for (int o = 16; o > 0; o >>= 1) m = fmaxf(m, __shfl_xor_sync(0xffffffffu, m, o));
    if ((threadIdx.x & 31) == 0) s_r2w[threadIdx.x >> 5] = m;
    __syncthreads();
    if (threadIdx.x == 0) {
        float mm = s_r2w[0];
#pragma unroll
        for (int w = 1; w < TILE_PTS / 32; ++w) mm = fmaxf(mm, s_r2w[w]);
        g_r2max[t0] = mm;
    }

    g_r2[pos] = r2lane;
    if (valid) {
        float2* o = &g_cand[0][pos * KNN];
#pragma unroll
        for (int j = 0; j < KNN; ++j)
            o[j] = make_float2(bd[j], __int_as_float(bi[j]));
    }
}

// ------------------------- tile candidate lists -------------------------------
__global__ void __launch_bounds__(160) tile_list_kernel()
{
    const int t0 = blockIdx.x;
    const int t  = threadIdx.x;
    if (t >= NT) return;
    if (t == t0) return;
    const float r2m = g_r2max[t0];
    float4 amn = g_bbmin[t0], amx = g_bbmax[t0];
    float4 bmn = g_bbmin[t],  bmx = g_bbmax[t];
    float dx = fmaxf(fmaxf(bmn.x - amx.x, amn.x - bmx.x), 0.f);
    float dy = fmaxf(fmaxf(bmn.y - amx.y, amn.y - bmx.y), 0.f);
    float dz = fmaxf(fmaxf(bmn.z - amx.z, amn.z - bmx.z), 0.f);
    float d2 = dx * dx + dy * dy + dz * dz;
    if (d2 <= r2m) {
        int k = atomicAdd(&g_tcnt[t0], 1);
        g_tlist[t0 * NT + k] = t;
    }
}

// ------------------------- pass B: remaining tiles, radius-pruned -------------
__global__ void __launch_bounds__(TILE_PTS) knn_split_kernel()
{
    const int split = blockIdx.y;
    const int t0    = blockIdx.x;
    const int pos   = t0 * TILE_PTS + threadIdx.x;
    const bool valid = (pos < N_POINTS);
    float4 me = g_spts[pos];
    const float qx = me.x, qy = me.y, qz = me.z;
    const float r2 = g_r2[pos];           // 0 for pads -> never needed
    const int cnt = g_tcnt[t0];

    float bd[KNN];
    int   bi[KNN];
#pragma unroll
    for (int j = 0; j < KNN; ++j) { bd[j] = 3.4e38f; bi[j] = -1; }

    for (int idx = split; idx < cnt; idx += NSPB) {
        const int t = g_tlist[t0 * NT + idx];
        float4 bmn = g_bbmin[t];
        float4 bmx = g_bbmax[t];
        float dx = fmaxf(fmaxf(bmn.x - qx, qx - bmx.x), 0.f);
        float dy = fmaxf(fmaxf(bmn.y - qy, qy - bmx.y), 0.f);
        float dz = fmaxf(fmaxf(bmn.z - qz, qz - bmx.z), 0.f);
        float dmin2 = dx * dx + dy * dy + dz * dz;
        bool need = valid && (dmin2 <= fminf(r2, bd[KNN - 1]));
        if (__ballot_sync(0xffffffffu, need) == 0u) continue;

        const float4* __restrict__ tp = g_spts + t * TILE_PTS;
#pragma unroll 1
        for (int i = 0; i < TILE_PTS; i += 8) {
            float4 c[8];
#pragma unroll
            for (int u = 0; u < 8; ++u) c[u] = tp[i + u];
            float dd[8];
#pragma unroll
            for (int u = 0; u < 8; ++u) {
                float ddx = qx - c[u].x, ddy = qy - c[u].y, ddz = qz - c[u].z;
                dd[u] = fmaf(ddx, ddx, fmaf(ddy, ddy, ddz * ddz));
            }
#pragma unroll
            for (int u = 0; u < 8; ++u) TRY_INSERT_R(dd[u], t * TILE_PTS + i + u);
        }
    }

    if (valid) {
        float2* o = &g_cand[1 + split][pos * KNN];
#pragma unroll
        for (int j = 0; j < KNN; ++j)
            o[j] = make_float2(bd[j], __int_as_float(bi[j]));
    }
}

// ------------------------- 4-way merge ----------------------------------------
__global__ void knn_merge_kernel()
{
    const int pos = blockIdx.x * blockDim.x + threadIdx.x;
    if (pos >= N_POINTS) return;

    const float2* c0 = &g_cand[0][pos * KNN];
    const float2* c1 = &g_cand[1][pos * KNN];
    const float2* c2 = &g_cand[2][pos * KNN];
    const float2* c3 = &g_cand[3][pos * KNN];
    int h0 = 0, h1 = 0, h2 = 0, h3 = 0;
    float2 v0 = c0[0], v1 = c1[0], v2 = c2[0], v3 = c3[0];

#pragma unroll
    for (int j = 0; j < KNN; ++j) {
        int pick;
        if (v0.x <= v1.x && v0.x <= v2.x && v0.x <= v3.x)      pick = __float_as_int(v0.y);
        else if (v1.x <= v2.x && v1.x <= v3.x)                 pick = __float_as_int(v1.y);
        else if (v2.x <= v3.x)                                 pick = __float_as_int(v2.y);
        else                                                   pick = __float_as_int(v3.y);
        g_knn[pos * KNN + j] = pick;
        if (v0.x <= v1.x && v0.x <= v2.x && v0.x <= v3.x)      v0 = (++h0 < KNN) ? c0[h0] : make_float2(3.4e38f, 0.f);
        else if (v1.x <= v2.x && v1.x <= v3.x)                 v1 = (++h1 < KNN) ? c1[h1] : make_float2(3.4e38f, 0.f);
        else if (v2.x <= v3.x)                                 v2 = (++h2 < KNN) ? c2[h2] : make_float2(3.4e38f, 0.f);
        else                                                   v3 = (++h3 < KNN) ? c3[h3] : make_float2(3.4e38f, 0.f);
    }
}

// ------------------------- softmax init + logits sort -------------------------
__global__ void softmax_init_kernel(const float* __restrict__ logits)
{
    const int pos = blockIdx.x * blockDim.x + threadIdx.x;
    if (pos >= N_POINTS) return;
    const int orig = __float_as_int(g_spts[pos].w);

    float v[NUM_CLASSES];
    const float4* lr = reinterpret_cast<const float4*>(logits + orig * NUM_CLASSES);
#pragma unroll
    for (int c = 0; c < NUM_CLASSES / 4; ++c) {
        float4 x = lr[c];
        v[4*c+0] = x.x; v[4*c+1] = x.y; v[4*c+2] = x.z; v[4*c+3] = x.w;
    }
    // sorted-order logits copy
    float4* ls = reinterpret_cast<float4*>(&g_logits_s[pos * NUM_CLASSES]);
#pragma unroll
    for (int c = 0; c < NUM_CLASSES / 4; ++c)
        ls[c] = make_float4(v[4*c+0], v[4*c+1], v[4*c+2], v[4*c+3]);

    float mx = v[0];
#pragma unroll
    for (int c = 1; c < NUM_CLASSES; ++c) mx = fmaxf(mx, v[c]);
    float s = 0.f;
#pragma unroll
    for (int c = 0; c < NUM_CLASSES; ++c) { v[c] = __expf(v[c] - mx); s += v[c]; }
    const float inv = 1.f / s;
    float4* qr = reinterpret_cast<float4*>(&g_q[0][pos * NUM_CLASSES]);
#pragma unroll
    for (int c = 0; c < NUM_CLASSES / 4; ++c)
        qr[c] = make_float4(v[4*c+0]*inv, v[4*c+1]*inv, v[4*c+2]*inv, v[4*c+3]*inv);
}

// ------------------------- CRF step: 2 threads per point ----------------------
__global__ void __launch_bounds__(256) crf_step_kernel(
    const float* __restrict__ W,
    int src_buf, int dst_buf,
    float* __restrict__ refined_out,
    float* __restrict__ q_out)
{
    __shared__ float sW[NUM_CLASSES * NUM_CLASSES];
    for (int t = threadIdx.x; t < NUM_CLASSES * NUM_CLASSES; t += blockDim.x) sW[t] = W[t];
    __syncthreads();

    const int g = blockIdx.x * blockDim.x + threadIdx.x;
    const int i = g >> 1;          // sorted position
    const int sub = g & 1;
    if (i >= N_POINTS) return;

    const float* __restrict__ qsrc = g_q[src_buf];

    const int4* kr = reinterpret_cast<const int4*>(&g_knn[i * KNN]);
    int4 k0 = kr[0], k1 = kr[1], k2 = kr[2], k3 = kr[3];
    int nb[KNN] = {k0.x, k0.y, k0.z, k0.w, k1.x, k1.y, k1.z, k1.w,
                   k2.x, k2.y, k2.z, k2.w, k3.x, k3.y, k3.z, k3.w};

    const int half = 10;
    float msg[half];
#pragma unroll
    for (int c = 0; c < half; ++c) msg[c] = 0.f;

#pragma unroll
    for (int j = 0; j < KNN; ++j) {
        const float2* qr = reinterpret_cast<const float2*>(qsrc + nb[j] * NUM_CLASSES + sub * half);
#pragma unroll
        for (int c = 0; c < half / 2; ++c) {
            float2 x = qr[c];
            msg[2*c+0] += x.x; msg[2*c+1] += x.y;
        }
    }
#pragma unroll
    for (int c = 0; c < half; ++c) msg[c] *= (1.0f / KNN);

    float mall[NUM_CLASSES];
#pragma unroll
    for (int c = 0; c < half; ++c) {
        float other = __shfl_xor_sync(0xffffffffu, msg[c], 1);
        mall[c]        = sub ? other  : msg[c];
        mall[half + c] = sub ? msg[c] : other;
    }

    float ref[half];
    {
        const float2* lr = reinterpret_cast<const float2*>(g_logits_s + i * NUM_CLASSES + sub * half);
#pragma unroll
        for (int c = 0; c < half / 2; ++c) {
            float2 x = lr[c];
            ref[2*c+0] = x.x; ref[2*c+1] = x.y;
        }
    }
    const int c0 = sub * half;
#pragma unroll
    for (int c = 0; c < half; ++c) {
        float acc = ref[c];
#pragma unroll
        for (int j = 0; j < NUM_CLASSES; ++j)
            acc = fmaf(mall[j], sW[(c0 + c) * NUM_CLASSES + j], acc);
        ref[c] = acc;
    }

    float mx = ref[0];
#pragma unroll
    for (int c = 1; c < half; ++c) mx = fmaxf(mx, ref[c]);
    mx = fmaxf(mx, __shfl_xor_sync(0xffffffffu, mx, 1));
    float e[half];
    float s = 0.f;
#pragma unroll
    for (int c = 0; c < half; ++c) { e[c] = __expf(ref[c] - mx); s += e[c]; }
    s += __shfl_xor_sync(0xffffffffu, s, 1);
    const float inv = 1.f / s;

    float2* qd = reinterpret_cast<float2*>(&g_q[dst_buf][i * NUM_CLASSES + sub * half]);
#pragma unroll
    for (int c = 0; c < half / 2; ++c)
        qd[c] = make_float2(e[2*c+0] * inv, e[2*c+1] * inv);

    if (refined_out != nullptr) {
        const int orig = __float_as_int(g_spts[i].w);
        float2* ro = reinterpret_cast<float2*>(refined_out + orig * NUM_CLASSES + sub * half);
        float2* qo = reinterpret_cast<float2*>(q_out + orig * NUM_CLASSES + sub * half);
#pragma unroll
        for (int c = 0; c < half / 2; ++c) {
            ro[c] = make_float2(ref[2*c+0], ref[2*c+1]);
            qo[c] = make_float2(e[2*c+0] * inv, e[2*c+1] * inv);
        }
    }
}

// ------------------------- launch ---------------------------------------------
extern "C" void kernel_launch(void* const* d_in, const int* in_sizes, int n_in,
                              void* d_out, int out_size)
{
    const float* logits = (const float*)d_in[0];  // (20000, 20)
    const float* coords = (const float*)d_in[1];  // (20000, 3)
    const float* compat = (const float*)d_in[2];  // (20, 20)
    float* out = (float*)d_out;                   // refined (400000) then q (400000)
    (void)in_sizes; (void)n_in; (void)out_size;

    // spatial counting sort by morton cell
    clear_kernel<<<(NCELLS + 255) / 256, 256>>>();
    hist_kernel<<<(N_POINTS + 255) / 256, 256>>>(coords);
    scan_kernel<<<1, 256>>>();
    scatter_kernel<<<(N_POINTS + 255) / 256, 256>>>(coords);
    bbox_kernel<<<(NT * 32 + 127) / 128, 128>>>();

    // exact KNN: own-tile radius bound -> tile lists -> pruned pass -> merge
    knn_own_kernel<<<NT, TILE_PTS>>>();
    tile_list_kernel<<<NT, 160>>>();
    dim3 kg(NT, NSPB);
    knn_split_kernel<<<kg, TILE_PTS>>>();
    knn_merge_kernel<<<(N_POINTS + 255) / 256, 256>>>();

    // CRF in sorted space (2 threads per point)
    softmax_init_kernel<<<(N_POINTS + 255) / 256, 256>>>(logits);
    const int crf_threads = 2 * N_POINTS;
    crf_step_kernel<<<(crf_threads + 255) / 256, 256>>>(compat, 0, 1, nullptr, nullptr);
    crf_step_kernel<<<(crf_threads + 255) / 256, 256>>>(compat, 1, 0, nullptr, nullptr);
    crf_step_kernel<<<(crf_threads + 255) / 256, 256>>>(compat, 0, 1,
                                                        out, out + N_POINTS * NUM_CLASSES);
}

// round 5
// speedup vs baseline: 5.2719x; 1.3965x over previous
#include <cuda_runtime.h>
#include <math.h>

#define N_POINTS    20000
#define NUM_CLASSES 20
#define KNN         16
#define NCELL_AX    16
#define NCELLS      4096

// ------------------------- device scratch (no allocs) -----------------------
__device__ int    g_counts[NCELLS];
__device__ int    g_off[NCELLS];
__device__ float4 g_spts[N_POINTS];   // sorted points: x,y,z, orig-index bits
__device__ int    g_knn[N_POINTS * KNN];              // neighbor SORTED positions
__device__ float  g_logits_s[N_POINTS * NUM_CLASSES]; // logits in sorted order
__device__ float  g_q[2][N_POINTS * NUM_CLASSES];     // q in sorted order

// ------------------------- morton helpers ------------------------------------
__device__ __forceinline__ unsigned part1by2(unsigned v) {
    v &= 0x3ff;
    v = (v | (v << 16)) & 0x030000FF;
    v = (v | (v << 8))  & 0x0300F00F;
    v = (v | (v << 4))  & 0x030C30C3;
    v = (v | (v << 2))  & 0x09249249;
    return v;
}
__device__ __forceinline__ int clamp16(int v) { return min(NCELL_AX - 1, max(0, v)); }
__device__ __forceinline__ int cell_of(float x, float y, float z) {
    int cx = clamp16((int)(x * NCELL_AX));
    int cy = clamp16((int)(y * NCELL_AX));
    int cz = clamp16((int)(z * NCELL_AX));
    return (int)(part1by2(cx) | (part1by2(cy) << 1) | (part1by2(cz) << 2));
}

// ------------------------- fused counting sort (single block) -----------------
__global__ void __launch_bounds__(1024) sort_kernel(const float* __restrict__ coords)
{
    __shared__ int s_cnt[NCELLS];
    __shared__ int s_off[NCELLS];
    __shared__ int s_w[32];
    const int tid = threadIdx.x;

    for (int c = tid; c < NCELLS; c += 1024) s_cnt[c] = 0;
    __syncthreads();

    for (int i = tid; i < N_POINTS; i += 1024) {
        int c = cell_of(coords[3 * i], coords[3 * i + 1], coords[3 * i + 2]);
        atomicAdd(&s_cnt[c], 1);
    }
    __syncthreads();

    // block exclusive scan over 4096 counts (4 cells/thread)
    const int b = tid * 4;
    int c0 = s_cnt[b], c1 = s_cnt[b + 1], c2 = s_cnt[b + 2], c3 = s_cnt[b + 3];
    int sum = c0 + c1 + c2 + c3;
    int v = sum;
#pragma unroll
    for (int o = 1; o < 32; o <<= 1) {
        int n = __shfl_up_sync(0xffffffffu, v, o);
        if ((tid & 31) >= o) v += n;
    }
    if ((tid & 31) == 31) s_w[tid >> 5] = v;
    __syncthreads();
    if (tid < 32) {
        int vv = s_w[tid];
#pragma unroll
        for (int o = 1; o < 32; o <<= 1) {
            int n = __shfl_up_sync(0xffffffffu, vv, o);
            if (tid >= o) vv += n;
        }
        s_w[tid] = vv;   // inclusive warp sums
    }
    __syncthreads();
    int wb = (tid >= 32) ? s_w[(tid >> 5) - 1] : 0;
    int excl = wb + v - sum;
    s_off[b]     = excl;
    s_off[b + 1] = excl + c0;
    s_off[b + 2] = excl + c0 + c1;
    s_off[b + 3] = excl + c0 + c1 + c2;
    g_off[b] = s_off[b]; g_off[b + 1] = s_off[b + 1];
    g_off[b + 2] = s_off[b + 2]; g_off[b + 3] = s_off[b + 3];
    g_counts[b] = c0; g_counts[b + 1] = c1; g_counts[b + 2] = c2; g_counts[b + 3] = c3;
    __syncthreads();

    // scatter (s_off becomes cursor)
    for (int i = tid; i < N_POINTS; i += 1024) {
        float x = coords[3 * i], y = coords[3 * i + 1], z = coords[3 * i + 2];
        int c = cell_of(x, y, z);
        int pos = atomicAdd(&s_off[c], 1);
        g_spts[pos] = make_float4(x, y, z, __int_as_float(i));
    }
}

// ------------------------- exact cell-based KNN -------------------------------
#define TRY_INSERT(DD, II)                                              \
    do {                                                                \
        float _d = (DD); int _i = (II);                                 \
        if (_d < bd[KNN - 1]) {                                         \
            _Pragma("unroll")                                           \
            for (int _j = 0; _j < KNN; ++_j) {                          \
                if (_d < bd[_j]) {                                      \
                    float _tf = bd[_j]; bd[_j] = _d; _d = _tf;          \
                    int   _ti = bi[_j]; bi[_j] = _i; _i = _ti;          \
                }                                                       \
            }                                                           \
        }                                                               \
    } while (0)

__global__ void __launch_bounds__(256) knn_cell_kernel()
{
    const int pos = blockIdx.x * blockDim.x + threadIdx.x;
    if (pos >= N_POINTS) return;
    const float4 me = g_spts[pos];
    const float qx = me.x, qy = me.y, qz = me.z;
    const int cx = clamp16((int)(qx * NCELL_AX));
    const int cy = clamp16((int)(qy * NCELL_AX));
    const int cz = clamp16((int)(qz * NCELL_AX));
    const float h = 1.0f / NCELL_AX;

    float bd[KNN];
    int   bi[KNN];
#pragma unroll
    for (int j = 0; j < KNN; ++j) { bd[j] = 3.4e38f; bi[j] = -1; }

    // ring-1 block scan (skip, don't clamp, out-of-range planes)
    {
        const int x0 = max(0, cx - 1), x1 = min(NCELL_AX - 1, cx + 1);
        const int y0 = max(0, cy - 1), y1 = min(NCELL_AX - 1, cy + 1);
        const int z0 = max(0, cz - 1), z1 = min(NCELL_AX - 1, cz + 1);
        for (int z = z0; z <= z1; ++z) {
            const unsigned mz = part1by2((unsigned)z) << 2;
            for (int y = y0; y <= y1; ++y) {
                const unsigned my = part1by2((unsigned)y) << 1;
                for (int x = x0; x <= x1; ++x) {
                    const unsigned c = part1by2((unsigned)x) | my | mz;
                    const int s = g_off[c];
                    const int e = s + g_counts[c];
                    for (int p = s; p < e; ++p) {
                        float4 cd = g_spts[p];
                        float dx = qx - cd.x, dy = qy - cd.y, dz = qz - cd.z;
                        float d2 = fmaf(dx, dx, fmaf(dy, dy, dz * dz));
                        TRY_INSERT(d2, p);
                    }
                }
            }
        }
    }

    // exactness check + rare shell expansion
    int R = 1;
    while (true) {
        float m = 1e9f;
        if (cx - R > 0)             m = fminf(m, qx - (float)(cx - R) * h);
        if (cx + R < NCELL_AX - 1)  m = fminf(m, (float)(cx + R + 1) * h - qx);
        if (cy - R > 0)             m = fminf(m, qy - (float)(cy - R) * h);
        if (cy + R < NCELL_AX - 1)  m = fminf(m, (float)(cy + R + 1) * h - qy);
        if (cz - R > 0)             m = fminf(m, qz - (float)(cz - R) * h);
        if (cz + R < NCELL_AX - 1)  m = fminf(m, (float)(cz + R + 1) * h - qz);
        if (bd[KNN - 1] < m * m) break;   // m==1e9 (whole grid scanned) also breaks

        ++R;  // scan chebyshev shell == R
        const int x0 = max(0, cx - R), x1 = min(NCELL_AX - 1, cx + R);
        const int y0 = max(0, cy - R), y1 = min(NCELL_AX - 1, cy + R);
        const int z0 = max(0, cz - R), z1 = min(NCELL_AX - 1, cz + R);
        for (int z = z0; z <= z1; ++z) {
            const int az = abs(z - cz);
            const unsigned mz = part1by2((unsigned)z) << 2;
            for (int y = y0; y <= y1; ++y) {
                const int ay = max(az, abs(y - cy));
                const unsigned my = part1by2((unsigned)y) << 1;
                for (int x = x0; x <= x1; ++x) {
                    if (max(ay, abs(x - cx)) != R) continue;  // shell only
                    const unsigned c = part1by2((unsigned)x) | my | mz;
                    const int s = g_off[c];
                    const int e = s + g_counts[c];
                    for (int p = s; p < e; ++p) {
                        float4 cd = g_spts[p];
                        float dx = qx - cd.x, dy = qy - cd.y, dz = qz - cd.z;
                        float d2 = fmaf(dx, dx, fmaf(dy, dy, dz * dz));
                        TRY_INSERT(d2, p);
                    }
                }
            }
        }
    }

#pragma unroll
    for (int j = 0; j < KNN; ++j) g_knn[pos * KNN + j] = bi[j];
}

// ------------------------- softmax init + logits sort -------------------------
__global__ void softmax_init_kernel(const float* __restrict__ logits)
{
    const int pos = blockIdx.x * blockDim.x + threadIdx.x;
    if (pos >= N_POINTS) return;
    const int orig = __float_as_int(g_spts[pos].w);

    float v[NUM_CLASSES];
    const float4* lr = reinterpret_cast<const float4*>(logits + orig * NUM_CLASSES);
#pragma unroll
    for (int c = 0; c < NUM_CLASSES / 4; ++c) {
        float4 x = lr[c];
        v[4*c+0] = x.x; v[4*c+1] = x.y; v[4*c+2] = x.z; v[4*c+3] = x.w;
    }
    float4* ls = reinterpret_cast<float4*>(&g_logits_s[pos * NUM_CLASSES]);
#pragma unroll
    for (int c = 0; c < NUM_CLASSES / 4; ++c)
        ls[c] = make_float4(v[4*c+0], v[4*c+1], v[4*c+2], v[4*c+3]);

    float mx = v[0];
#pragma unroll
    for (int c = 1; c < NUM_CLASSES; ++c) mx = fmaxf(mx, v[c]);
    float s = 0.f;
#pragma unroll
    for (int c = 0; c < NUM_CLASSES; ++c) { v[c] = __expf(v[c] - mx); s += v[c]; }
    const float inv = 1.f / s;
    float4* qr = reinterpret_cast<float4*>(&g_q[0][pos * NUM_CLASSES]);
#pragma unroll
    for (int c = 0; c < NUM_CLASSES / 4; ++c)
        qr[c] = make_float4(v[4*c+0]*inv, v[4*c+1]*inv, v[4*c+2]*inv, v[4*c+3]*inv);
}

// ------------------------- CRF step: 2 threads per point ----------------------
__global__ void __launch_bounds__(256) crf_step_kernel(
    const float* __restrict__ W,
    int src_buf, int dst_buf,
    float* __restrict__ refined_out,
    float* __restrict__ q_out)
{
    __shared__ float sW[NUM_CLASSES * NUM_CLASSES];
    for (int t = threadIdx.x; t < NUM_CLASSES * NUM_CLASSES; t += blockDim.x) sW[t] = W[t];
    __syncthreads();

    const int g = blockIdx.x * blockDim.x + threadIdx.x;
    const int i = g >> 1;          // sorted position
    const int sub = g & 1;
    if (i >= N_POINTS) return;

    const float* __restrict__ qsrc = g_q[src_buf];

    const int4* kr = reinterpret_cast<const int4*>(&g_knn[i * KNN]);
    int4 k0 = kr[0], k1 = kr[1], k2 = kr[2], k3 = kr[3];
    int nb[KNN] = {k0.x, k0.y, k0.z, k0.w, k1.x, k1.y, k1.z, k1.w,
                   k2.x, k2.y, k2.z, k2.w, k3.x, k3.y, k3.z, k3.w};

    const int half = 10;
    float msg[half];
#pragma unroll
    for (int c = 0; c < half; ++c) msg[c] = 0.f;

#pragma unroll
    for (int j = 0; j < KNN; ++j) {
        const float2* qr = reinterpret_cast<const float2*>(qsrc + nb[j] * NUM_CLASSES + sub * half);
#pragma unroll
        for (int c = 0; c < half / 2; ++c) {
            float2 x = qr[c];
            msg[2*c+0] += x.x; msg[2*c+1] += x.y;
        }
    }
#pragma unroll
    for (int c = 0; c < half; ++c) msg[c] *= (1.0f / KNN);

    float mall[NUM_CLASSES];
#pragma unroll
    for (int c = 0; c < half; ++c) {
        float other = __shfl_xor_sync(0xffffffffu, msg[c], 1);
        mall[c]        = sub ? other  : msg[c];
        mall[half + c] = sub ? msg[c] : other;
    }

    float ref[half];
    {
        const float2* lr = reinterpret_cast<const float2*>(g_logits_s + i * NUM_CLASSES + sub * half);
#pragma unroll
        for (int c = 0; c < half / 2; ++c) {
            float2 x = lr[c];
            ref[2*c+0] = x.x; ref[2*c+1] = x.y;
        }
    }
    const int c0 = sub * half;
#pragma unroll
    for (int c = 0; c < half; ++c) {
        float acc = ref[c];
#pragma unroll
        for (int j = 0; j < NUM_CLASSES; ++j)
            acc = fmaf(mall[j], sW[(c0 + c) * NUM_CLASSES + j], acc);
        ref[c] = acc;
    }

    float mx = ref[0];
#pragma unroll
    for (int c = 1; c < half; ++c) mx = fmaxf(mx, ref[c]);
    mx = fmaxf(mx, __shfl_xor_sync(0xffffffffu, mx, 1));
    float e[half];
    float s = 0.f;
#pragma unroll
    for (int c = 0; c < half; ++c) { e[c] = __expf(ref[c] - mx); s += e[c]; }
    s += __shfl_xor_sync(0xffffffffu, s, 1);
    const float inv = 1.f / s;

    float2* qd = reinterpret_cast<float2*>(&g_q[dst_buf][i * NUM_CLASSES + sub * half]);
#pragma unroll
    for (int c = 0; c < half / 2; ++c)
        qd[c] = make_float2(e[2*c+0] * inv, e[2*c+1] * inv);

    if (refined_out != nullptr) {
        const int orig = __float_as_int(g_spts[i].w);
        float2* ro = reinterpret_cast<float2*>(refined_out + orig * NUM_CLASSES + sub * half);
        float2* qo = reinterpret_cast<float2*>(q_out + orig * NUM_CLASSES + sub * half);
#pragma unroll
        for (int c = 0; c < half / 2; ++c) {
            ro[c] = make_float2(ref[2*c+0], ref[2*c+1]);
            qo[c] = make_float2(e[2*c+0] * inv, e[2*c+1] * inv);
        }
    }
}

// ------------------------- launch ---------------------------------------------
extern "C" void kernel_launch(void* const* d_in, const int* in_sizes, int n_in,
                              void* d_out, int out_size)
{
    const float* logits = (const float*)d_in[0];  // (20000, 20)
    const float* coords = (const float*)d_in[1];  // (20000, 3)
    const float* compat = (const float*)d_in[2];  // (20, 20)
    float* out = (float*)d_out;                   // refined (400000) then q (400000)
    (void)in_sizes; (void)n_in; (void)out_size;

    // 1) fused counting sort by morton cell (single block)
    sort_kernel<<<1, 1024>>>(coords);

    // 2) exact cell-based KNN
    knn_cell_kernel<<<(N_POINTS + 255) / 256, 256>>>();

    // 3) CRF in sorted space
    softmax_init_kernel<<<(N_POINTS + 255) / 256, 256>>>(logits);
    const int crf_threads = 2 * N_POINTS;
    crf_step_kernel<<<(crf_threads + 255) / 256, 256>>>(compat, 0, 1, nullptr, nullptr);
    crf_step_kernel<<<(crf_threads + 255) / 256, 256>>>(compat, 1, 0, nullptr, nullptr);
    crf_step_kernel<<<(crf_threads + 255) / 256, 256>>>(compat, 0, 1,
                                                        out, out + N_POINTS * NUM_CLASSES);
}

// round 6
// speedup vs baseline: 7.6218x; 1.4457x over previous
#include <cuda_runtime.h>
#include <math.h>

#define N_POINTS    20000
#define NUM_CLASSES 20
#define KNN         16
#define NCELL_AX    16
#define NCELLS      4096

// ------------------------- device scratch (no allocs) -----------------------
__device__ int    g_off[NCELLS + 1];   // prefix offsets, g_off[NCELLS] = N
__device__ int    g_cursor[NCELLS];
__device__ float4 g_spts[N_POINTS];    // sorted points
__device__ int    g_orig[N_POINTS];    // sorted pos -> original index
__device__ int    g_knn[N_POINTS * KNN];              // neighbor SORTED positions
__device__ float  g_logits_s[N_POINTS * NUM_CLASSES]; // logits in sorted order
__device__ float  g_q[2][N_POINTS * NUM_CLASSES];     // q in sorted order

__device__ __forceinline__ int clamp16(int v) { return min(NCELL_AX - 1, max(0, v)); }
__device__ __forceinline__ int cell_lin(float x, float y, float z) {
    int cx = clamp16((int)(x * NCELL_AX));
    int cy = clamp16((int)(y * NCELL_AX));
    int cz = clamp16((int)(z * NCELL_AX));
    return cx + (cy << 4) + (cz << 8);
}

// ------------------------- prep: clear + hist + scan (1 block) ----------------
__global__ void __launch_bounds__(1024) prep_kernel(const float* __restrict__ coords)
{
    __shared__ int s_cnt[NCELLS];
    __shared__ int s_w[32];
    const int tid = threadIdx.x;

    for (int c = tid; c < NCELLS; c += 1024) s_cnt[c] = 0;
    __syncthreads();

    for (int i = tid; i < N_POINTS; i += 1024) {
        int c = cell_lin(coords[3 * i], coords[3 * i + 1], coords[3 * i + 2]);
        atomicAdd(&s_cnt[c], 1);
    }
    __syncthreads();

    // exclusive scan over 4096 counts, 4 cells/thread
    const int b = tid * 4;
    int c0 = s_cnt[b], c1 = s_cnt[b + 1], c2 = s_cnt[b + 2], c3 = s_cnt[b + 3];
    int sum = c0 + c1 + c2 + c3;
    int v = sum;
#pragma unroll
    for (int o = 1; o < 32; o <<= 1) {
        int n = __shfl_up_sync(0xffffffffu, v, o);
        if ((tid & 31) >= o) v += n;
    }
    if ((tid & 31) == 31) s_w[tid >> 5] = v;
    __syncthreads();
    if (tid < 32) {
        int vv = s_w[tid];
#pragma unroll
        for (int o = 1; o < 32; o <<= 1) {
            int n = __shfl_up_sync(0xffffffffu, vv, o);
            if (tid >= o) vv += n;
        }
        s_w[tid] = vv;
    }
    __syncthreads();
    int wb = (tid >= 32) ? s_w[(tid >> 5) - 1] : 0;
    int excl = wb + v - sum;
    int o0 = excl, o1 = excl + c0, o2 = o1 + c1, o3 = o2 + c2;
    g_off[b] = o0; g_off[b + 1] = o1; g_off[b + 2] = o2; g_off[b + 3] = o3;
    g_cursor[b] = o0; g_cursor[b + 1] = o1; g_cursor[b + 2] = o2; g_cursor[b + 3] = o3;
    if (tid == 0) g_off[NCELLS] = N_POINTS;
}

// ------------------------- scatter + softmax init (fused) ---------------------
__global__ void __launch_bounds__(256) scatter_kernel(const float* __restrict__ coords,
                                                      const float* __restrict__ logits)
{
    const int i = blockIdx.x * blockDim.x + threadIdx.x;
    if (i >= N_POINTS) return;
    const float x = coords[3 * i], y = coords[3 * i + 1], z = coords[3 * i + 2];
    const int c = cell_lin(x, y, z);
    const int pos = atomicAdd(&g_cursor[c], 1);
    g_spts[pos] = make_float4(x, y, z, 0.f);
    g_orig[pos] = i;

    float v[NUM_CLASSES];
    const float4* lr = reinterpret_cast<const float4*>(logits + i * NUM_CLASSES);
#pragma unroll
    for (int cc = 0; cc < NUM_CLASSES / 4; ++cc) {
        float4 xv = lr[cc];
        v[4*cc+0] = xv.x; v[4*cc+1] = xv.y; v[4*cc+2] = xv.z; v[4*cc+3] = xv.w;
    }
    float4* ls = reinterpret_cast<float4*>(&g_logits_s[pos * NUM_CLASSES]);
#pragma unroll
    for (int cc = 0; cc < NUM_CLASSES / 4; ++cc)
        ls[cc] = make_float4(v[4*cc+0], v[4*cc+1], v[4*cc+2], v[4*cc+3]);

    float mx = v[0];
#pragma unroll
    for (int cc = 1; cc < NUM_CLASSES; ++cc) mx = fmaxf(mx, v[cc]);
    float s = 0.f;
#pragma unroll
    for (int cc = 0; cc < NUM_CLASSES; ++cc) { v[cc] = __expf(v[cc] - mx); s += v[cc]; }
    const float inv = 1.f / s;
    float4* qr = reinterpret_cast<float4*>(&g_q[0][pos * NUM_CLASSES]);
#pragma unroll
    for (int cc = 0; cc < NUM_CLASSES / 4; ++cc)
        qr[cc] = make_float4(v[4*cc+0]*inv, v[4*cc+1]*inv, v[4*cc+2]*inv, v[4*cc+3]*inv);
}

// ------------------------- exact KNN: 2 threads/query, row ranges -------------
#define TRY_INSERT(DD, II)                                              \
    do {                                                                \
        float _d = (DD); int _i = (II);                                 \
        if (_d < bd[KNN - 1]) {                                         \
            _Pragma("unroll")                                           \
            for (int _j = 0; _j < KNN; ++_j) {                          \
                if (_d < bd[_j]) {                                      \
                    float _tf = bd[_j]; bd[_j] = _d; _d = _tf;          \
                    int   _ti = bi[_j]; bi[_j] = _i; _i = _ti;          \
                }                                                       \
            }                                                           \
        }                                                               \
    } while (0)

__global__ void __launch_bounds__(256) knn_kernel()
{
    const int g = blockIdx.x * blockDim.x + threadIdx.x;
    if (g >= 2 * N_POINTS) return;        // 40000 % 32 == 0: whole warps exit
    const int pos = g >> 1;
    const int sub = g & 1;

    const float4 me = g_spts[pos];
    const float qx = me.x, qy = me.y, qz = me.z;
    const int cx = clamp16((int)(qx * NCELL_AX));
    const int cy = clamp16((int)(qy * NCELL_AX));
    const int cz = clamp16((int)(qz * NCELL_AX));
    const float h = 1.0f / NCELL_AX;

    float bd[KNN];
    int   bi[KNN];
#pragma unroll
    for (int j = 0; j < KNN; ++j) { bd[j] = 3.4e38f; bi[j] = -1; }

    auto scan_range = [&](int s, int e) {
        int p = s;
        for (; p + 1 < e; p += 2) {
            float4 c0 = g_spts[p];
            float4 c1 = g_spts[p + 1];
            float dx0 = qx - c0.x, dy0 = qy - c0.y, dz0 = qz - c0.z;
            float dx1 = qx - c1.x, dy1 = qy - c1.y, dz1 = qz - c1.z;
            float d0 = fmaf(dx0, dx0, fmaf(dy0, dy0, dz0 * dz0));
            float d1 = fmaf(dx1, dx1, fmaf(dy1, dy1, dz1 * dz1));
            TRY_INSERT(d0, p);
            TRY_INSERT(d1, p + 1);
        }
        if (p < e) {
            float4 c0 = g_spts[p];
            float dx0 = qx - c0.x, dy0 = qy - c0.y, dz0 = qz - c0.z;
            float d0 = fmaf(dx0, dx0, fmaf(dy0, dy0, dz0 * dz0));
            TRY_INSERT(d0, p);
        }
    };

    // ring-1: rows (z,y), x-range contiguous; rows split by parity between pair
    {
        const int x0 = max(0, cx - 1), x1 = min(NCELL_AX - 1, cx + 1);
        const int y0 = max(0, cy - 1), y1 = min(NCELL_AX - 1, cy + 1);
        const int z0 = max(0, cz - 1), z1 = min(NCELL_AX - 1, cz + 1);
        int k = 0;
        for (int z = z0; z <= z1; ++z)
            for (int y = y0; y <= y1; ++y) {
                if ((k++ & 1) != sub) continue;
                const int base = (z << 8) + (y << 4);
                scan_range(g_off[base + x0], g_off[base + x1 + 1]);
            }
    }

    // exactness check on MERGED list + rare shell expansion
    int R = 1;
    while (true) {
        float wk = 0.f;
#pragma unroll
        for (int j = 0; j < KNN; ++j) {
            float od = __shfl_xor_sync(0xffffffffu, bd[KNN - 1 - j], 1);
            wk = fmaxf(wk, fminf(bd[j], od));
        }
        float m = 1e9f;
        if (cx - R > 0)             m = fminf(m, qx - (float)(cx - R) * h);
        if (cx + R < NCELL_AX - 1)  m = fminf(m, (float)(cx + R + 1) * h - qx);
        if (cy - R > 0)             m = fminf(m, qy - (float)(cy - R) * h);
        if (cy + R < NCELL_AX - 1)  m = fminf(m, (float)(cy + R + 1) * h - qy);
        if (cz - R > 0)             m = fminf(m, qz - (float)(cz - R) * h);
        if (cz + R < NCELL_AX - 1)  m = fminf(m, (float)(cz + R + 1) * h - qz);
        if (wk < m * m) break;

        ++R;  // scan chebyshev shell == R, rows split by parity
        const int x0 = max(0, cx - R), x1 = min(NCELL_AX - 1, cx + R);
        const int y0 = max(0, cy - R), y1 = min(NCELL_AX - 1, cy + R);
        const int z0 = max(0, cz - R), z1 = min(NCELL_AX - 1, cz + R);
        int k = 0;
        for (int z = z0; z <= z1; ++z) {
            const int az = abs(z - cz);
            for (int y = y0; y <= y1; ++y) {
                const int ay = max(az, abs(y - cy));
                const int base = (z << 8) + (y << 4);
                if (ay == R) {
                    if ((k++ & 1) == sub)
                        scan_range(g_off[base + x0], g_off[base + x1 + 1]);
                } else {
                    if (cx - R >= 0 && (k++ & 1) == sub)
                        scan_range(g_off[base + cx - R], g_off[base + cx - R + 1]);
                    if (cx + R <= NCELL_AX - 1 && (k++ & 1) == sub)
                        scan_range(g_off[base + cx + R], g_off[base + cx + R + 1]);
                }
            }
        }
    }

    // final merge: top16(A∪B)[j] = min(a[j], b[15-j]); only the SET matters
    int mi[KNN];
#pragma unroll
    for (int j = 0; j < KNN; ++j) {
        float od = __shfl_xor_sync(0xffffffffu, bd[KNN - 1 - j], 1);
        int   oi = __shfl_xor_sync(0xffffffffu, bi[KNN - 1 - j], 1);
        mi[j] = (bd[j] <= od) ? bi[j] : oi;
    }
    if (sub == 0) {
        int4* o = reinterpret_cast<int4*>(&g_knn[pos * KNN]);
#pragma unroll
        for (int j = 0; j < KNN / 4; ++j)
            o[j] = make_int4(mi[4*j], mi[4*j+1], mi[4*j+2], mi[4*j+3]);
    }
}

// ------------------------- CRF step: 4 threads per point ----------------------
__global__ void __launch_bounds__(256) crf_step_kernel(
    const float* __restrict__ W,
    int src_buf, int dst_buf,
    float* __restrict__ refined_out,
    float* __restrict__ q_out)
{
    __shared__ float sW[NUM_CLASSES * NUM_CLASSES];
    for (int t = threadIdx.x; t < NUM_CLASSES * NUM_CLASSES; t += blockDim.x) sW[t] = W[t];
    __syncthreads();

    const int g = blockIdx.x * blockDim.x + threadIdx.x;
    if (g >= 4 * N_POINTS) return;   // 80000 % 32 == 0: whole warps exit
    const int i  = g >> 2;           // sorted position
    const int t4 = g & 3;

    const float* __restrict__ qsrc = g_q[src_buf];

    // this thread gathers 4 of the 16 neighbours (full 20 classes, float4)
    const int4 nb = reinterpret_cast<const int4*>(&g_knn[i * KNN])[t4];
    float msg[NUM_CLASSES];
#pragma unroll
    for (int c = 0; c < NUM_CLASSES; ++c) msg[c] = 0.f;

#define GATHER(NB)                                                          \
    do {                                                                    \
        const float4* qr = reinterpret_cast<const float4*>(qsrc + (NB) * NUM_CLASSES); \
        float4 a0 = qr[0], a1 = qr[1], a2 = qr[2], a3 = qr[3], a4 = qr[4];  \
        msg[0]+=a0.x; msg[1]+=a0.y; msg[2]+=a0.z; msg[3]+=a0.w;             \
        msg[4]+=a1.x; msg[5]+=a1.y; msg[6]+=a1.z; msg[7]+=a1.w;             \
        msg[8]+=a2.x; msg[9]+=a2.y; msg[10]+=a2.z; msg[11]+=a2.w;           \
        msg[12]+=a3.x; msg[13]+=a3.y; msg[14]+=a3.z; msg[15]+=a3.w;         \
        msg[16]+=a4.x; msg[17]+=a4.y; msg[18]+=a4.z; msg[19]+=a4.w;         \
    } while (0)
    GATHER(nb.x); GATHER(nb.y); GATHER(nb.z); GATHER(nb.w);
#undef GATHER

    // butterfly-reduce partial sums across the 4 sub-threads
#pragma unroll
    for (int c = 0; c < NUM_CLASSES; ++c) {
        msg[c] += __shfl_xor_sync(0xffffffffu, msg[c], 1);
        msg[c] += __shfl_xor_sync(0xffffffffu, msg[c], 2);
        msg[c] *= (1.0f / KNN);
    }

    // refined for my 5 classes
    const int c0 = t4 * 5;
    float ref[5];
#pragma unroll
    for (int c = 0; c < 5; ++c) {
        float acc = g_logits_s[i * NUM_CLASSES + c0 + c];
#pragma unroll
        for (int j = 0; j < NUM_CLASSES; ++j)
            acc = fmaf(msg[j], sW[(c0 + c) * NUM_CLASSES + j], acc);
        ref[c] = acc;
    }

    // softmax across the 4 sub-threads
    float mx = ref[0];
#pragma unroll
    for (int c = 1; c < 5; ++c) mx = fmaxf(mx, ref[c]);
    mx = fmaxf(mx, __shfl_xor_sync(0xffffffffu, mx, 1));
    mx = fmaxf(mx, __shfl_xor_sync(0xffffffffu, mx, 2));
    float e[5];
    float s = 0.f;
#pragma unroll
    for (int c = 0; c < 5; ++c) { e[c] = __expf(ref[c] - mx); s += e[c]; }
    s += __shfl_xor_sync(0xffffffffu, s, 1);
    s += __shfl_xor_sync(0xffffffffu, s, 2);
    const float inv = 1.f / s;

    float* qd = &g_q[dst_buf][i * NUM_CLASSES + c0];
#pragma unroll
    for (int c = 0; c < 5; ++c) qd[c] = e[c] * inv;

    if (refined_out != nullptr) {
        const int orig = g_orig[i];
        float* ro = refined_out + orig * NUM_CLASSES + c0;
        float* qo = q_out       + orig * NUM_CLASSES + c0;
#pragma unroll
        for (int c = 0; c < 5; ++c) {
            ro[c] = ref[c];
            qo[c] = e[c] * inv;
        }
    }
}

// ------------------------- launch ---------------------------------------------
extern "C" void kernel_launch(void* const* d_in, const int* in_sizes, int n_in,
                              void* d_out, int out_size)
{
    const float* logits = (const float*)d_in[0];  // (20000, 20)
    const float* coords = (const float*)d_in[1];  // (20000, 3)
    const float* compat = (const float*)d_in[2];  // (20, 20)
    float* out = (float*)d_out;                   // refined (400000) then q (400000)
    (void)in_sizes; (void)n_in; (void)out_size;

    // 1) clear + histogram + scan (single block)
    prep_kernel<<<1, 1024>>>(coords);
    // 2) scatter + softmax init + logits permutation (fused)
    scatter_kernel<<<(N_POINTS + 255) / 256, 256>>>(coords, logits);
    // 3) exact KNN, 2 threads/query
    knn_kernel<<<(2 * N_POINTS + 255) / 256, 256>>>();
    // 4-6) CRF, 4 threads/point
    const int crf_threads = 4 * N_POINTS;
    crf_step_kernel<<<(crf_threads + 255) / 256, 256>>>(compat, 0, 1, nullptr, nullptr);
    crf_step_kernel<<<(crf_threads + 255) / 256, 256>>>(compat, 1, 0, nullptr, nullptr);
    crf_step_kernel<<<(crf_threads + 255) / 256, 256>>>(compat, 0, 1,
                                                        out, out + N_POINTS * NUM_CLASSES);
}

// round 7
// speedup vs baseline: 10.6705x; 1.4000x over previous
#include <cuda_runtime.h>
#include <math.h>

#define N_POINTS    20000
#define NUM_CLASSES 20
#define KNN         16
#define NCELL_AX    16
#define NCELLS      4096

// ------------------------- device scratch (no allocs) -----------------------
__device__ int    g_off[NCELLS + 1];
__device__ int    g_cursor[NCELLS];
__device__ float4 g_spts[N_POINTS];
__device__ int    g_orig[N_POINTS];
__device__ int    g_knn[N_POINTS * KNN];
__device__ float  g_logits_s[N_POINTS * NUM_CLASSES];
__device__ float  g_q[2][N_POINTS * NUM_CLASSES];

__device__ __forceinline__ int clamp16(int v) { return min(NCELL_AX - 1, max(0, v)); }
__device__ __forceinline__ int cell_lin(float x, float y, float z) {
    int cx = clamp16((int)(x * NCELL_AX));
    int cy = clamp16((int)(y * NCELL_AX));
    int cz = clamp16((int)(z * NCELL_AX));
    return cx + (cy << 4) + (cz << 8);
}

// ------------------------- prep: clear + hist + scan (1 block) ----------------
__global__ void __launch_bounds__(1024) prep_kernel(const float* __restrict__ coords)
{
    __shared__ int s_cnt[NCELLS];
    __shared__ int s_w[32];
    const int tid = threadIdx.x;

    for (int c = tid; c < NCELLS; c += 1024) s_cnt[c] = 0;
    __syncthreads();
    for (int i = tid; i < N_POINTS; i += 1024) {
        int c = cell_lin(coords[3 * i], coords[3 * i + 1], coords[3 * i + 2]);
        atomicAdd(&s_cnt[c], 1);
    }
    __syncthreads();

    const int b = tid * 4;
    int c0 = s_cnt[b], c1 = s_cnt[b + 1], c2 = s_cnt[b + 2], c3 = s_cnt[b + 3];
    int sum = c0 + c1 + c2 + c3;
    int v = sum;
#pragma unroll
    for (int o = 1; o < 32; o <<= 1) {
        int n = __shfl_up_sync(0xffffffffu, v, o);
        if ((tid & 31) >= o) v += n;
    }
    if ((tid & 31) == 31) s_w[tid >> 5] = v;
    __syncthreads();
    if (tid < 32) {
        int vv = s_w[tid];
#pragma unroll
        for (int o = 1; o < 32; o <<= 1) {
            int n = __shfl_up_sync(0xffffffffu, vv, o);
            if (tid >= o) vv += n;
        }
        s_w[tid] = vv;
    }
    __syncthreads();
    int wb = (tid >= 32) ? s_w[(tid >> 5) - 1] : 0;
    int excl = wb + v - sum;
    int o0 = excl, o1 = excl + c0, o2 = o1 + c1, o3 = o2 + c2;
    g_off[b] = o0; g_off[b + 1] = o1; g_off[b + 2] = o2; g_off[b + 3] = o3;
    g_cursor[b] = o0; g_cursor[b + 1] = o1; g_cursor[b + 2] = o2; g_cursor[b + 3] = o3;
    if (tid == 0) g_off[NCELLS] = N_POINTS;
}

// ------------------------- scatter + softmax init (fused) ---------------------
__global__ void __launch_bounds__(256) scatter_kernel(const float* __restrict__ coords,
                                                      const float* __restrict__ logits)
{
    const int i = blockIdx.x * blockDim.x + threadIdx.x;
    if (i >= N_POINTS) return;
    const float x = coords[3 * i], y = coords[3 * i + 1], z = coords[3 * i + 2];
    const int c = cell_lin(x, y, z);
    const int pos = atomicAdd(&g_cursor[c], 1);
    g_spts[pos] = make_float4(x, y, z, 0.f);
    g_orig[pos] = i;

    float v[NUM_CLASSES];
    const float4* lr = reinterpret_cast<const float4*>(logits + i * NUM_CLASSES);
#pragma unroll
    for (int cc = 0; cc < NUM_CLASSES / 4; ++cc) {
        float4 xv = lr[cc];
        v[4*cc+0] = xv.x; v[4*cc+1] = xv.y; v[4*cc+2] = xv.z; v[4*cc+3] = xv.w;
    }
    float4* ls = reinterpret_cast<float4*>(&g_logits_s[pos * NUM_CLASSES]);
#pragma unroll
    for (int cc = 0; cc < NUM_CLASSES / 4; ++cc)
        ls[cc] = make_float4(v[4*cc+0], v[4*cc+1], v[4*cc+2], v[4*cc+3]);

    float mx = v[0];
#pragma unroll
    for (int cc = 1; cc < NUM_CLASSES; ++cc) mx = fmaxf(mx, v[cc]);
    float s = 0.f;
#pragma unroll
    for (int cc = 0; cc < NUM_CLASSES; ++cc) { v[cc] = __expf(v[cc] - mx); s += v[cc]; }
    const float inv = 1.f / s;
    float4* qr = reinterpret_cast<float4*>(&g_q[0][pos * NUM_CLASSES]);
#pragma unroll
    for (int cc = 0; cc < NUM_CLASSES / 4; ++cc)
        qr[cc] = make_float4(v[4*cc+0]*inv, v[4*cc+1]*inv, v[4*cc+2]*inv, v[4*cc+3]*inv);
}

// ------------------------- exact KNN: 4 threads/query -------------------------
#define TRY_INSERT(DD, II)                                              \
    do {                                                                \
        float _d = (DD); int _i = (II);                                 \
        if (_d < bd[KNN - 1]) {                                         \
            _Pragma("unroll")                                           \
            for (int _j = 0; _j < KNN; ++_j) {                          \
                if (_d < bd[_j]) {                                      \
                    float _tf = bd[_j]; bd[_j] = _d; _d = _tf;          \
                    int   _ti = bi[_j]; bi[_j] = _i; _i = _ti;          \
                }                                                       \
            }                                                           \
        }                                                               \
    } while (0)

__global__ void __launch_bounds__(256) knn_kernel()
{
    const int g = blockIdx.x * blockDim.x + threadIdx.x;
    if (g >= 4 * N_POINTS) return;            // 80000 % 32 == 0: whole warps exit
    const int pos = g >> 2;
    const int sub = g & 3;
    const unsigned gm = 0xFu << (threadIdx.x & 28);   // 4-lane group mask

    const float4 me = g_spts[pos];
    const float qx = me.x, qy = me.y, qz = me.z;
    const int cx = clamp16((int)(qx * NCELL_AX));
    const int cy = clamp16((int)(qy * NCELL_AX));
    const int cz = clamp16((int)(qz * NCELL_AX));
    const float h = 1.0f / NCELL_AX;

    float bd[KNN];
    int   bi[KNN];
#pragma unroll
    for (int j = 0; j < KNN; ++j) { bd[j] = 3.4e38f; bi[j] = -1; }

    // sub-thread takes positions p ≡ sub (mod 4) within each row: balanced + coalesced
    auto scan_row = [&](int s, int e) {
        int p = s + sub;
        for (; p + 4 < e; p += 8) {
            float4 c0 = g_spts[p];
            float4 c1 = g_spts[p + 4];
            float dx0 = qx - c0.x, dy0 = qy - c0.y, dz0 = qz - c0.z;
            float dx1 = qx - c1.x, dy1 = qy - c1.y, dz1 = qz - c1.z;
            float d0 = fmaf(dx0, dx0, fmaf(dy0, dy0, dz0 * dz0));
            float d1 = fmaf(dx1, dx1, fmaf(dy1, dy1, dz1 * dz1));
            TRY_INSERT(d0, p);
            TRY_INSERT(d1, p + 4);
        }
        if (p < e) {
            float4 c0 = g_spts[p];
            float dx0 = qx - c0.x, dy0 = qy - c0.y, dz0 = qz - c0.z;
            float d0 = fmaf(dx0, dx0, fmaf(dy0, dy0, dz0 * dz0));
            TRY_INSERT(d0, p);
        }
    };

    // ring-1: up to 9 contiguous x-rows
    {
        const int x0 = max(0, cx - 1), x1 = min(NCELL_AX - 1, cx + 1);
        const int y0 = max(0, cy - 1), y1 = min(NCELL_AX - 1, cy + 1);
        const int z0 = max(0, cz - 1), z1 = min(NCELL_AX - 1, cz + 1);
        for (int z = z0; z <= z1; ++z)
            for (int y = y0; y <= y1; ++y) {
                const int base = (z << 8) + (y << 4);
                scan_row(g_off[base + x0], g_off[base + x1 + 1]);
            }
    }

    // exactness check (tight union bound) + rare shell expansion
    int R = 1;
    while (true) {
        // 16th of (this ∪ xor-1 partner): max_j min(a[j], b[15-j]); then min across pairs
        float w = 0.f;
#pragma unroll
        for (int j = 0; j < KNN; ++j) {
            float od = __shfl_xor_sync(gm, bd[KNN - 1 - j], 1);
            w = fmaxf(w, fminf(bd[j], od));
        }
        w = fminf(w, __shfl_xor_sync(gm, w, 2));

        float m = 1e9f;
        if (cx - R > 0)             m = fminf(m, qx - (float)(cx - R) * h);
        if (cx + R < NCELL_AX - 1)  m = fminf(m, (float)(cx + R + 1) * h - qx);
        if (cy - R > 0)             m = fminf(m, qy - (float)(cy - R) * h);
        if (cy + R < NCELL_AX - 1)  m = fminf(m, (float)(cy + R + 1) * h - qy);
        if (cz - R > 0)             m = fminf(m, qz - (float)(cz - R) * h);
        if (cz + R < NCELL_AX - 1)  m = fminf(m, (float)(cz + R + 1) * h - qz);
        if (w < m * m) break;     // m==1e9 (whole grid scanned) also breaks

        ++R;   // chebyshev shell == R
        const int x0 = max(0, cx - R), x1 = min(NCELL_AX - 1, cx + R);
        const int y0 = max(0, cy - R), y1 = min(NCELL_AX - 1, cy + R);
        const int z0 = max(0, cz - R), z1 = min(NCELL_AX - 1, cz + R);
        for (int z = z0; z <= z1; ++z) {
            const int az = abs(z - cz);
            for (int y = y0; y <= y1; ++y) {
                const int ay = max(az, abs(y - cy));
                const int base = (z << 8) + (y << 4);
                if (ay == R) {
                    scan_row(g_off[base + x0], g_off[base + x1 + 1]);
                } else {
                    if (cx - R >= 0)
                        scan_row(g_off[base + cx - R], g_off[base + cx - R + 1]);
                    if (cx + R <= NCELL_AX - 1)
                        scan_row(g_off[base + cx + R], g_off[base + cx + R + 1]);
                }
            }
        }
    }

    // merge the 4 disjoint sorted lists:
    // stage 1 (xor 1): half-cleaner -> bitonic; bitonic-clean sort; stage 2 (xor 2): half-cleaner
    float md[KNN]; int mi_[KNN];
#pragma unroll
    for (int j = 0; j < KNN; ++j) {
        float od = __shfl_xor_sync(gm, bd[KNN - 1 - j], 1);
        int   oi = __shfl_xor_sync(gm, bi[KNN - 1 - j], 1);
        bool p = bd[j] <= od;
        md[j]  = p ? bd[j] : od;
        mi_[j] = p ? bi[j] : oi;
    }
#pragma unroll
    for (int d = 8; d >= 1; d >>= 1) {
#pragma unroll
        for (int j = 0; j < KNN; ++j) {
            if (!(j & d)) {
                bool p = md[j] <= md[j + d];
                float dlo = p ? md[j] : md[j + d];
                float dhi = p ? md[j + d] : md[j];
                int   ilo = p ? mi_[j] : mi_[j + d];
                int   ihi = p ? mi_[j + d] : mi_[j];
                md[j] = dlo; md[j + d] = dhi;
                mi_[j] = ilo; mi_[j + d] = ihi;
            }
        }
    }
    int fi[KNN];
#pragma unroll
    for (int j = 0; j < KNN; ++j) {
        float od = __shfl_xor_sync(gm, md[KNN - 1 - j], 2);
        int   oi = __shfl_xor_sync(gm, mi_[KNN - 1 - j], 2);
        fi[j] = (md[j] <= od) ? mi_[j] : oi;
    }
    if (sub == 0) {
        int4* o = reinterpret_cast<int4*>(&g_knn[pos * KNN]);
#pragma unroll
        for (int j = 0; j < KNN / 4; ++j)
            o[j] = make_int4(fi[4*j], fi[4*j+1], fi[4*j+2], fi[4*j+3]);
    }
}

// ------------------------- CRF step: 8 threads per point ----------------------
__global__ void __launch_bounds__(256) crf_step_kernel(
    const float* __restrict__ W,
    int src_buf, int dst_buf,
    float* __restrict__ refined_out,
    float* __restrict__ q_out)
{
    __shared__ float sW[NUM_CLASSES * NUM_CLASSES];
    for (int t = threadIdx.x; t < NUM_CLASSES * NUM_CLASSES; t += blockDim.x) sW[t] = W[t];
    __syncthreads();

    const int g = blockIdx.x * blockDim.x + threadIdx.x;   // grid exactly 8*N
    const int i  = g >> 3;            // sorted position
    const int t8 = g & 7;

    const float* __restrict__ qsrc = g_q[src_buf];

    // gather 2 of 16 neighbours (full 20 classes each)
    const int2 nb = reinterpret_cast<const int2*>(&g_knn[i * KNN])[t8];
    float msg[NUM_CLASSES];
#pragma unroll
    for (int c = 0; c < NUM_CLASSES; ++c) msg[c] = 0.f;

#define GATHER(NB)                                                          \
    do {                                                                    \
        const float4* qr = reinterpret_cast<const float4*>(qsrc + (NB) * NUM_CLASSES); \
        float4 a0 = qr[0], a1 = qr[1], a2 = qr[2], a3 = qr[3], a4 = qr[4];  \
        msg[0]+=a0.x; msg[1]+=a0.y; msg[2]+=a0.z; msg[3]+=a0.w;             \
        msg[4]+=a1.x; msg[5]+=a1.y; msg[6]+=a1.z; msg[7]+=a1.w;             \
        msg[8]+=a2.x; msg[9]+=a2.y; msg[10]+=a2.z; msg[11]+=a2.w;           \
        msg[12]+=a3.x; msg[13]+=a3.y; msg[14]+=a3.z; msg[15]+=a3.w;         \
        msg[16]+=a4.x; msg[17]+=a4.y; msg[18]+=a4.z; msg[19]+=a4.w;         \
    } while (0)
    GATHER(nb.x); GATHER(nb.y);
#undef GATHER

    // butterfly over the 8 sub-threads
#pragma unroll
    for (int c = 0; c < NUM_CLASSES; ++c) {
        msg[c] += __shfl_xor_sync(0xffffffffu, msg[c], 1);
        msg[c] += __shfl_xor_sync(0xffffffffu, msg[c], 2);
        msg[c] += __shfl_xor_sync(0xffffffffu, msg[c], 4);
        msg[c] *= (1.0f / KNN);
    }

    // class split: threads 0-3 -> 3 classes, threads 4-7 -> 2 classes
    const int nc   = (t8 < 4) ? 3 : 2;
    const int base = (t8 < 4) ? t8 * 3 : 12 + (t8 - 4) * 2;

    float ref[3];
#pragma unroll
    for (int c = 0; c < 3; ++c) {
        if (c < nc) {
            float acc = g_logits_s[i * NUM_CLASSES + base + c];
#pragma unroll
            for (int j = 0; j < NUM_CLASSES; ++j)
                acc = fmaf(msg[j], sW[(base + c) * NUM_CLASSES + j], acc);
            ref[c] = acc;
        }
    }

    // softmax across the 8 sub-threads
    float mx = ref[0];
    if (nc == 3) mx = fmaxf(mx, ref[2]);
    mx = fmaxf(mx, ref[1]);
    mx = fmaxf(mx, __shfl_xor_sync(0xffffffffu, mx, 1));
    mx = fmaxf(mx, __shfl_xor_sync(0xffffffffu, mx, 2));
    mx = fmaxf(mx, __shfl_xor_sync(0xffffffffu, mx, 4));
    float e[3];
    float s = 0.f;
#pragma unroll
    for (int c = 0; c < 3; ++c)
        if (c < nc) { e[c] = __expf(ref[c] - mx); s += e[c]; }
    s += __shfl_xor_sync(0xffffffffu, s, 1);
    s += __shfl_xor_sync(0xffffffffu, s, 2);
    s += __shfl_xor_sync(0xffffffffu, s, 4);
    const float inv = 1.f / s;

    float* qd = &g_q[dst_buf][i * NUM_CLASSES + base];
#pragma unroll
    for (int c = 0; c < 3; ++c)
        if (c < nc) qd[c] = e[c] * inv;

    if (refined_out != nullptr) {
        const int orig = g_orig[i];
        float* ro = refined_out + orig * NUM_CLASSES + base;
        float* qo = q_out       + orig * NUM_CLASSES + base;
#pragma unroll
        for (int c = 0; c < 3; ++c)
            if (c < nc) { ro[c] = ref[c]; qo[c] = e[c] * inv; }
    }
}

// ------------------------- launch ---------------------------------------------
extern "C" void kernel_launch(void* const* d_in, const int* in_sizes, int n_in,
                              void* d_out, int out_size)
{
    const float* logits = (const float*)d_in[0];  // (20000, 20)
    const float* coords = (const float*)d_in[1];  // (20000, 3)
    const float* compat = (const float*)d_in[2];  // (20, 20)
    float* out = (float*)d_out;                   // refined (400000) then q (400000)
    (void)in_sizes; (void)n_in; (void)out_size;

    prep_kernel<<<1, 1024>>>(coords);
    scatter_kernel<<<(N_POINTS + 255) / 256, 256>>>(coords, logits);
    knn_kernel<<<(4 * N_POINTS + 255) / 256, 256>>>();
    crf_step_kernel<<<8 * N_POINTS / 256, 256>>>(compat, 0, 1, nullptr, nullptr);
    crf_step_kernel<<<8 * N_POINTS / 256, 256>>>(compat, 1, 0, nullptr, nullptr);
    crf_step_kernel<<<8 * N_POINTS / 256, 256>>>(compat, 0, 1,
                                                 out, out + N_POINTS * NUM_CLASSES);
}